// round 15
// baseline (speedup 1.0000x reference)
#include <cuda_runtime.h>
#include <cuda_fp16.h>
#include <math.h>
#include <stdint.h>

// ---------------------------------------------------------------------------
// Problem constants
// ---------------------------------------------------------------------------
#define BATCH 128
#define SEQ   49
#define FDIM  2048
#define D     768
#define KQ    100
#define NHEAD 8
#define HD    96
#define FF    2048
#define NC    1000
#define GRP   10
#define EPS   1e-5f
#define DKV   1536      // concatenated K|V width

// ---------------------------------------------------------------------------
// Scratch (static device globals; no allocation allowed)
// ---------------------------------------------------------------------------
__device__ __half g_xT  [BATCH * SEQ * FDIM];
__device__ __half g_memh[BATCH * SEQ * D];
__device__ __half g_ctxh[BATCH * KQ * D];
__device__ __half g_t2h [BATCH * KQ * D];
__device__ __half g_h1h [BATCH * KQ * FF];
__device__ __half g_tlnh[128 * D];             // fp16 tgt_ln padded to 128 rows
__device__ __half g_qh  [128 * D];             // fp16 q projection
__device__ __half g_kvh [BATCH * SEQ * DKV];   // fp16 K|V fused projection
__device__ __half g_tmph[BATCH * KQ * D];      // fp16 attn-out
__device__ __half g_h2h [BATCH * KQ * D];      // fp16 FFN out
// fp16 weights ([K, N] row-major); wkv = concat(wk, wv) along N
__device__ __half g_We [FDIM * D];
__device__ __half g_wq [D * D];
__device__ __half g_wkv[D * DKV];
__device__ __half g_wo [D * D];
__device__ __half g_w1 [D * FF];
__device__ __half g_w2 [FF * D];
__device__ float  g_bkv[DKV];
// fp32 buffers
__device__ float g_tgtln[KQ * D];
__device__ float g_tgt2 [BATCH * KQ * D];

// ---------------------------------------------------------------------------
// PTX helpers
// ---------------------------------------------------------------------------
__device__ __forceinline__ uint32_t smem_u32(const void* p) {
    return (uint32_t)__cvta_generic_to_shared(p);
}
__device__ __forceinline__ void ldsm_x4(uint32_t* d, uint32_t addr) {
    asm volatile("ldmatrix.sync.aligned.m8n8.x4.shared.b16 {%0,%1,%2,%3}, [%4];"
        : "=r"(d[0]), "=r"(d[1]), "=r"(d[2]), "=r"(d[3]) : "r"(addr));
}
__device__ __forceinline__ void ldsm_x4t(uint32_t* d, uint32_t addr) {
    asm volatile("ldmatrix.sync.aligned.m8n8.x4.trans.shared.b16 {%0,%1,%2,%3}, [%4];"
        : "=r"(d[0]), "=r"(d[1]), "=r"(d[2]), "=r"(d[3]) : "r"(addr));
}
__device__ __forceinline__ void mma16816h(float* c, const uint32_t* a, const uint32_t* b) {
    asm volatile("mma.sync.aligned.m16n8k16.row.col.f32.f16.f16.f32 "
        "{%0,%1,%2,%3}, {%4,%5,%6,%7}, {%8,%9}, {%0,%1,%2,%3};"
        : "+f"(c[0]), "+f"(c[1]), "+f"(c[2]), "+f"(c[3])
        : "r"(a[0]), "r"(a[1]), "r"(a[2]), "r"(a[3]), "r"(b[0]), "r"(b[1]));
}
__device__ __forceinline__ void mma16816h2(float* c, const uint32_t* a,
                                           uint32_t b0, uint32_t b1) {
    asm volatile("mma.sync.aligned.m16n8k16.row.col.f32.f16.f16.f32 "
        "{%0,%1,%2,%3}, {%4,%5,%6,%7}, {%8,%9}, {%0,%1,%2,%3};"
        : "+f"(c[0]), "+f"(c[1]), "+f"(c[2]), "+f"(c[3])
        : "r"(a[0]), "r"(a[1]), "r"(a[2]), "r"(a[3]), "r"(b0), "r"(b1));
}
__device__ __forceinline__ void cp_async16(uint32_t dst, const void* src) {
    asm volatile("cp.async.cg.shared.global [%0], [%1], 16;"
        :: "r"(dst), "l"(src) : "memory");
}
__device__ __forceinline__ void cp_commit() {
    asm volatile("cp.async.commit_group;" ::: "memory");
}
template<int N_>
__device__ __forceinline__ void cp_wait() {
    asm volatile("cp.async.wait_group %0;" :: "n"(N_) : "memory");
}

// ---------------------------------------------------------------------------
// Tensor-core GEMM tile (R7/R10-proven config, as device function)
// ---------------------------------------------------------------------------
#define TBM 128
#define TBN 128
#define TBK 32
#define NSTG 4
#define A_STRIDE (TBK + 8)      // 40 halfs
#define B_STRIDE (TBN + 8)      // 136 halfs
#define A_BUF (TBM * A_STRIDE)  // 5120 halfs
#define B_BUF (TBK * B_STRIDE)  // 4352 halfs
#define STAGE_HALFS (A_BUF + B_BUF)              // 9472
#define SMEM_GEMM (NSTG * STAGE_HALFS * 2)       // 75776 B

template<bool RELU, bool WF32, bool WHALF>
__device__ __forceinline__
void gemm_tile(const __half* __restrict__ A, const __half* __restrict__ B,
               const float* __restrict__ bias,
               float* __restrict__ Cf, __half* __restrict__ Ch,
               int N, int K, int m0, int n0, unsigned char* smem_raw)
{
    __half* sA = (__half*)smem_raw;               // [NSTG][A_BUF]
    __half* sB = sA + NSTG * A_BUF;               // [NSTG][B_BUF]

    const int tid  = threadIdx.x;
    const int lane = tid & 31;
    const int warp = tid >> 5;
    const int m_base = (warp & 1) * 64;
    const int n_base = (warp >> 1) * 32;

    const int ar = tid >> 2,  ac = (tid & 3) * 8;    // A: rows ar, ar+64
    const int br = tid >> 4,  bc = (tid & 15) * 8;   // B: rows br, br+16

    const uint32_t uA = smem_u32(sA);
    const uint32_t uB = smem_u32(sB);

    float acc[4][4][4];
    #pragma unroll
    for (int i = 0; i < 4; i++)
        #pragma unroll
        for (int j = 0; j < 4; j++)
            #pragma unroll
            for (int k = 0; k < 4; k++) acc[i][j][k] = 0.0f;

    auto load_async = [&](int it, int buf) {
        const int k0 = it * TBK;
        uint32_t dA = uA + (uint32_t)((buf * A_BUF + ar * A_STRIDE + ac) * 2);
        const __half* gA = A + (size_t)(m0 + ar) * K + k0 + ac;
        cp_async16(dA, gA);
        cp_async16(dA + (uint32_t)(64 * A_STRIDE * 2), gA + (size_t)64 * K);
        uint32_t dB = uB + (uint32_t)((buf * B_BUF + br * B_STRIDE + bc) * 2);
        const __half* gB = B + (size_t)(k0 + br) * N + n0 + bc;
        cp_async16(dB, gB);
        cp_async16(dB + (uint32_t)(16 * B_STRIDE * 2), gB + (size_t)16 * N);
    };

    const int lr = lane & 15;
    const int lc = lane >> 4;

    auto compute_k = [&](int buf, int kk) {
        uint32_t a[4][4], b[2][4];
        #pragma unroll
        for (int mt = 0; mt < 4; mt++) {
            uint32_t off = (uint32_t)((buf * A_BUF +
                (m_base + mt * 16 + lr) * A_STRIDE + kk + lc * 8) * 2);
            ldsm_x4(a[mt], uA + off);
        }
        #pragma unroll
        for (int ng = 0; ng < 2; ng++) {
            uint32_t off = (uint32_t)((buf * B_BUF +
                (kk + lr) * B_STRIDE + n_base + ng * 16 + lc * 8) * 2);
            ldsm_x4t(b[ng], uB + off);
        }
        #pragma unroll
        for (int mt = 0; mt < 4; mt++)
            #pragma unroll
            for (int ng = 0; ng < 2; ng++)
                #pragma unroll
                for (int h = 0; h < 2; h++)
                    mma16816h(acc[mt][ng * 2 + h], a[mt], &b[ng][2 * h]);
    };

    const int niter = K / TBK;
    #pragma unroll
    for (int s = 0; s < NSTG - 1; s++) {
        if (s < niter) load_async(s, s);
        cp_commit();
    }
    int buf = 0;
    for (int it = 0; it < niter; it++) {
        cp_wait<NSTG - 2>();
        __syncthreads();
        compute_k(buf, 0);
        const int nx = it + NSTG - 1;
        if (nx < niter) {
            int nbuf = buf - 1; if (nbuf < 0) nbuf += NSTG;
            load_async(nx, nbuf);
        }
        cp_commit();
        compute_k(buf, 16);
        if (++buf == NSTG) buf = 0;
    }

    // epilogue
    #pragma unroll
    for (int mt = 0; mt < 4; mt++) {
        int r0 = m0 + m_base + mt * 16 + (lane >> 2);
        #pragma unroll
        for (int j = 0; j < 4; j++) {
            int col = n0 + n_base + j * 8 + (lane & 3) * 2;
            float bx = bias[col], by = bias[col + 1];
            float* c = acc[mt][j];
            float v00 = c[0] + bx, v01 = c[1] + by;
            float v10 = c[2] + bx, v11 = c[3] + by;
            if (RELU) {
                v00 = fmaxf(v00, 0.f); v01 = fmaxf(v01, 0.f);
                v10 = fmaxf(v10, 0.f); v11 = fmaxf(v11, 0.f);
            }
            if (WF32) {
                *(float2*)(Cf + (size_t)r0 * N + col)       = make_float2(v00, v01);
                *(float2*)(Cf + (size_t)(r0 + 8) * N + col) = make_float2(v10, v11);
            }
            if (WHALF) {
                __half2 p0; p0.x = __float2half_rn(v00); p0.y = __float2half_rn(v01);
                __half2 p1; p1.x = __float2half_rn(v10); p1.y = __float2half_rn(v11);
                *(__half2*)(Ch + (size_t)r0 * N + col)       = p0;
                *(__half2*)(Ch + (size_t)(r0 + 8) * N + col) = p1;
            }
        }
    }
}

template<bool RELU, bool WF32, bool WHALF>
__global__ __launch_bounds__(256, 2)
void mma_gemm(const __half* __restrict__ A, const __half* __restrict__ B,
              const float* __restrict__ bias,
              float* __restrict__ Cf, __half* __restrict__ Ch,
              int M, int N, int K)
{
    extern __shared__ __align__(16) unsigned char smem_raw[];
    (void)M;
    gemm_tile<RELU, WF32, WHALF>(A, B, bias, Cf, Ch, N, K,
                                 blockIdx.y * TBM, blockIdx.x * TBN, smem_raw);
}

// Fused KV-projection + q-projection GEMM.
// grid = (12, 50): rows 0..48 = KV tiles (N=DKV), row 49 = q tiles (N=D, 6 used)
__global__ __launch_bounds__(256, 2)
void mma_gemm_kvq(const __half* __restrict__ Akv, const __half* __restrict__ Bkv,
                  const float* __restrict__ bkv, __half* __restrict__ Ckv,
                  const __half* __restrict__ Aq, const __half* __restrict__ Bq,
                  const float* __restrict__ bq, __half* __restrict__ Cq)
{
    extern __shared__ __align__(16) unsigned char smem_raw[];
    if (blockIdx.y < 49) {
        gemm_tile<false, false, true>(Akv, Bkv, bkv, nullptr, Ckv, DKV, D,
                                      blockIdx.y * TBM, blockIdx.x * TBN, smem_raw);
    } else {
        if (blockIdx.x >= D / TBN) return;
        gemm_tile<false, false, true>(Aq, Bq, bq, nullptr, Cq, D, D,
                                      0, blockIdx.x * TBN, smem_raw);
    }
}

// ---------------------------------------------------------------------------
// Merged preprocessing: one launch, range-dispatched blocks.
//   [0, 16384)              xT transpose+cvt (b = id>>7, f0 = (id&63)*32, s0 = ((id>>6)&1)*32)
//   [16384, 18304)          weight cvt (5 jobs x 384 blocks, grid-stride)
//   [18304, 19456)          wkv concat + bkv
//   [19456, 19584)          query LN (128 rows; rows >= KQ write fp16 zeros)
// ---------------------------------------------------------------------------
#define PP_XT   16384
#define PP_W    (PP_XT + 5 * 384)         // 18304
#define PP_WKV  (PP_W + 1152)             // 19456
#define PP_GRID (PP_WKV + 128)            // 19584

__global__ __launch_bounds__(256)
void preproc(const float* __restrict__ x, __half* __restrict__ xT,
             const float* __restrict__ W_embed, __half* __restrict__ We,
             const float* __restrict__ wo, __half* __restrict__ woc,
             const float* __restrict__ w1, __half* __restrict__ w1c,
             const float* __restrict__ w2, __half* __restrict__ w2c,
             const float* __restrict__ wq, __half* __restrict__ wqc,
             const float* __restrict__ wk, const float* __restrict__ wv,
             const float* __restrict__ bk, const float* __restrict__ bv,
             __half* __restrict__ wkvc, float* __restrict__ bkv,
             const float* __restrict__ qe, const float* __restrict__ g1,
             const float* __restrict__ be1, float* __restrict__ tln,
             __half* __restrict__ tlnh)
{
    __shared__ float sh[32 * 33];
    const int bid = blockIdx.x;
    const int t = threadIdx.x;

    if (bid < PP_XT) {
        // transpose + fp16 convert
        int b = bid >> 7;
        int rem = bid & 127;
        int f0 = (rem & 63) * 32, s0 = (rem >> 6) * 32;
        const float* xb = x + (size_t)b * FDIM * SEQ;
        int tx = t & 31, ty = t >> 5;
        #pragma unroll
        for (int i = ty; i < 32; i += 8) {
            int s = s0 + tx;
            sh[i * 33 + tx] = (s < SEQ) ? xb[(size_t)(f0 + i) * SEQ + s] : 0.f;
        }
        __syncthreads();
        #pragma unroll
        for (int i = ty; i < 32; i += 8) {
            int s = s0 + i, f = f0 + tx;
            if (s < SEQ)
                xT[((size_t)b * SEQ + s) * FDIM + f] = __float2half_rn(sh[tx * 33 + i]);
        }
    } else if (bid < PP_W) {
        int id = bid - PP_XT;
        int job = id / 384, blk = id % 384;
        const float* s; __half* d; int n;
        switch (job) {
            case 0: s = W_embed; d = We;  n = FDIM * D / 4; break;
            case 1: s = wo;      d = woc; n = D * D / 4;    break;
            case 2: s = w1;      d = w1c; n = D * FF / 4;   break;
            case 3: s = w2;      d = w2c; n = FF * D / 4;   break;
            default:s = wq;      d = wqc; n = D * D / 4;    break;
        }
        for (int i = blk * 256 + t; i < n; i += 384 * 256) {
            float4 v = ((const float4*)s)[i];
            __half2 h0, h1;
            h0.x = __float2half_rn(v.x); h0.y = __float2half_rn(v.y);
            h1.x = __float2half_rn(v.z); h1.y = __float2half_rn(v.w);
            ((__half2*)d)[i * 2]     = h0;
            ((__half2*)d)[i * 2 + 1] = h1;
        }
    } else if (bid < PP_WKV) {
        int gt = (bid - PP_W) * 256 + t;
        if (gt < DKV) bkv[gt] = (gt < D) ? bk[gt] : bv[gt - D];
        if (gt < D * DKV / 4) {
            int k = gt / (DKV / 4);
            int c4 = gt - k * (DKV / 4);
            int n = c4 * 4;
            const float* src = (n < D) ? (wk + (size_t)k * D + n)
                                       : (wv + (size_t)k * D + n - D);
            float4 v = *(const float4*)src;
            __half2 h0, h1;
            h0.x = __float2half_rn(v.x); h0.y = __float2half_rn(v.y);
            h1.x = __float2half_rn(v.z); h1.y = __float2half_rn(v.w);
            ((__half2*)wkvc)[gt * 2]     = h0;
            ((__half2*)wkvc)[gt * 2 + 1] = h1;
        }
    } else {
        // query LN (block-wide over 256 threads, 3 elems each)
        int r = bid - PP_WKV;
        if (r >= KQ) {
            #pragma unroll
            for (int i = 0; i < 3; i++)
                tlnh[(size_t)r * D + t + i * 256] = __float2half_rn(0.0f);
            return;
        }
        float v[3];
        float s = 0.0f;
        #pragma unroll
        for (int i = 0; i < 3; i++) { v[i] = 2.0f * qe[(size_t)r * D + t + i * 256]; s += v[i]; }
        // block reduction using sh
        int lane = t & 31, w = t >> 5;
        #pragma unroll
        for (int o = 16; o > 0; o >>= 1) s += __shfl_down_sync(0xffffffffu, s, o);
        if (lane == 0) sh[w] = s;
        __syncthreads();
        float ss = (t < 8) ? sh[t] : 0.0f;
        if (w == 0) {
            #pragma unroll
            for (int o = 4; o > 0; o >>= 1) ss += __shfl_down_sync(0xffffffffu, ss, o);
            if (lane == 0) sh[0] = ss;
        }
        __syncthreads();
        float mean = sh[0] * (1.0f / D);
        __syncthreads();
        float vs = 0.0f;
        #pragma unroll
        for (int i = 0; i < 3; i++) { float d2 = v[i] - mean; vs += d2 * d2; }
        #pragma unroll
        for (int o = 16; o > 0; o >>= 1) vs += __shfl_down_sync(0xffffffffu, vs, o);
        if (lane == 0) sh[w] = vs;
        __syncthreads();
        float vv = (t < 8) ? sh[t] : 0.0f;
        if (w == 0) {
            #pragma unroll
            for (int o = 4; o > 0; o >>= 1) vv += __shfl_down_sync(0xffffffffu, vv, o);
            if (lane == 0) sh[0] = vv;
        }
        __syncthreads();
        float inv = rsqrtf(sh[0] * (1.0f / D) + EPS);
        #pragma unroll
        for (int i = 0; i < 3; i++) {
            int c = t + i * 256;
            float o = (v[i] - mean) * inv * g1[c] + be1[c];
            tln[(size_t)r * D + c] = o;
            tlnh[(size_t)r * D + c] = __float2half_rn(o);
        }
    }
}

// ---------------------------------------------------------------------------
// out = LN(res[r % KQ] + inp_fp16[r]) ; warp-per-row, 8 rows/block.
// ---------------------------------------------------------------------------
__global__ __launch_bounds__(256)
void ln_residual_w(const float* __restrict__ res, const __half* __restrict__ inp,
                   const float* __restrict__ g, const float* __restrict__ be,
                   float* __restrict__ out, __half* __restrict__ oh)
{
    const int warp = threadIdx.x >> 5, lane = threadIdx.x & 31;
    long r = (long)blockIdx.x * 8 + warp;
    long rr = r % KQ;
    const float* rp = res + rr * D;
    const __half* ip = inp + r * D;

    float v[24];
    float s = 0.0f;
    #pragma unroll
    for (int i = 0; i < 24; i++) {
        int c = lane + i * 32;
        v[i] = rp[c] + __half2float(ip[c]);
        s += v[i];
    }
    #pragma unroll
    for (int o = 16; o > 0; o >>= 1) s += __shfl_xor_sync(0xffffffffu, s, o);
    float mean = s * (1.0f / D);
    float vs = 0.0f;
    #pragma unroll
    for (int i = 0; i < 24; i++) { float d = v[i] - mean; vs += d * d; }
    #pragma unroll
    for (int o = 16; o > 0; o >>= 1) vs += __shfl_xor_sync(0xffffffffu, vs, o);
    float inv = rsqrtf(vs * (1.0f / D) + EPS);
    #pragma unroll
    for (int i = 0; i < 24; i++) {
        int c = lane + i * 32;
        float o = (v[i] - mean) * inv * g[c] + be[c];
        out[r * D + c] = o;
        oh[r * D + c] = __float2half_rn(o);
    }
}

// ---------------------------------------------------------------------------
// Tensor-core cross attention (R13-proven). grid=(NHEAD, BATCH), 128 threads.
// ---------------------------------------------------------------------------
#define AST 104                                // smem row stride (halfs)
#define SMEM_ATTN ((128 + 64 + 64) * AST * 2)  // 53248 B

__global__ __launch_bounds__(128)
void attn_mma(const __half* __restrict__ Q, const __half* __restrict__ KV,
              __half* __restrict__ ch)
{
    extern __shared__ __align__(16) __half smA[];
    __half* Qs = smA;                 // [128][AST]
    __half* Ks = Qs + 128 * AST;      // [64][AST] (rows >= SEQ zero)
    __half* Vs = Ks + 64 * AST;       // [64][AST] (rows >= SEQ zero)
    const int hh = blockIdx.x, b = blockIdx.y;
    const int t = threadIdx.x;
    const int lane = t & 31, warp = t >> 5;

    for (int idx = t; idx < 128 * 48; idx += 128) {
        int r = idx / 48, d2 = idx - r * 48;
        ((__half2*)(Qs + r * AST))[d2] =
            *(const __half2*)(Q + (size_t)r * D + hh * HD + 2 * d2);
    }
    for (int idx = t; idx < 64 * 48; idx += 128) {
        int s = idx / 48, d2 = idx - s * 48;
        __half2 kk2, vv2;
        if (s < SEQ) {
            size_t off = ((size_t)b * SEQ + s) * DKV + hh * HD + 2 * d2;
            kk2 = *(const __half2*)(KV + off);
            vv2 = *(const __half2*)(KV + off + D);
        } else {
            kk2.x = __float2half_rn(0.f); kk2.y = kk2.x;
            vv2 = kk2;
        }
        ((__half2*)(Ks + s * AST))[d2] = kk2;
        ((__half2*)(Vs + s * AST))[d2] = vv2;
    }
    __syncthreads();

    const int lr = lane & 15, lc = lane >> 4;
    const int m_base = warp * 32;
    const uint32_t uQ = smem_u32(Qs), uK = smem_u32(Ks), uV = smem_u32(Vs);

    float sacc[2][8][4];
    #pragma unroll
    for (int i = 0; i < 2; i++)
        #pragma unroll
        for (int j = 0; j < 8; j++)
            #pragma unroll
            for (int k = 0; k < 4; k++) sacc[i][j][k] = 0.0f;

    #pragma unroll
    for (int kk = 0; kk < HD; kk += 16) {
        uint32_t a[2][4];
        #pragma unroll
        for (int mt = 0; mt < 2; mt++)
            ldsm_x4(a[mt], uQ + (uint32_t)(((m_base + mt * 16 + lr) * AST + kk + lc * 8) * 2));
        uint32_t kb[4][4];
        #pragma unroll
        for (int ng = 0; ng < 4; ng++)
            ldsm_x4(kb[ng], uK + (uint32_t)(((ng * 16 + lr) * AST + kk + lc * 8) * 2));
        #pragma unroll
        for (int mt = 0; mt < 2; mt++)
            #pragma unroll
            for (int ng = 0; ng < 4; ng++) {
                mma16816h2(sacc[mt][2 * ng],     a[mt], kb[ng][0], kb[ng][2]);
                mma16816h2(sacc[mt][2 * ng + 1], a[mt], kb[ng][1], kb[ng][3]);
            }
    }

    const float scale = 0.102062072615966f;   // 1/sqrt(96)
    const int c0 = (lane & 3) * 2;
    float minv[2][2];
    #pragma unroll
    for (int mt = 0; mt < 2; mt++) {
        float m0 = -1e30f, m1 = -1e30f;
        #pragma unroll
        for (int j = 0; j < 8; j++) {
            int n = j * 8 + c0;
            float* c = sacc[mt][j];
            c[0] = (n     < SEQ) ? c[0] * scale : -1e30f;
            c[1] = (n + 1 < SEQ) ? c[1] * scale : -1e30f;
            c[2] = (n     < SEQ) ? c[2] * scale : -1e30f;
            c[3] = (n + 1 < SEQ) ? c[3] * scale : -1e30f;
            m0 = fmaxf(m0, fmaxf(c[0], c[1]));
            m1 = fmaxf(m1, fmaxf(c[2], c[3]));
        }
        m0 = fmaxf(m0, __shfl_xor_sync(0xffffffffu, m0, 1));
        m0 = fmaxf(m0, __shfl_xor_sync(0xffffffffu, m0, 2));
        m1 = fmaxf(m1, __shfl_xor_sync(0xffffffffu, m1, 1));
        m1 = fmaxf(m1, __shfl_xor_sync(0xffffffffu, m1, 2));
        float l0 = 0.f, l1 = 0.f;
        #pragma unroll
        for (int j = 0; j < 8; j++) {
            float* c = sacc[mt][j];
            c[0] = expf(c[0] - m0); c[1] = expf(c[1] - m0);
            c[2] = expf(c[2] - m1); c[3] = expf(c[3] - m1);
            l0 += c[0] + c[1];
            l1 += c[2] + c[3];
        }
        l0 += __shfl_xor_sync(0xffffffffu, l0, 1);
        l0 += __shfl_xor_sync(0xffffffffu, l0, 2);
        l1 += __shfl_xor_sync(0xffffffffu, l1, 1);
        l1 += __shfl_xor_sync(0xffffffffu, l1, 2);
        minv[mt][0] = 1.0f / l0;
        minv[mt][1] = 1.0f / l1;
    }

    float cacc[2][12][4];
    #pragma unroll
    for (int i = 0; i < 2; i++)
        #pragma unroll
        for (int j = 0; j < 12; j++)
            #pragma unroll
            for (int k = 0; k < 4; k++) cacc[i][j][k] = 0.0f;

    #pragma unroll
    for (int kt = 0; kt < 4; kt++) {
        uint32_t pa[2][4];
        #pragma unroll
        for (int mt = 0; mt < 2; mt++) {
            __half2 h;
            h = __floats2half2_rn(sacc[mt][2 * kt][0],     sacc[mt][2 * kt][1]);
            pa[mt][0] = *(uint32_t*)&h;
            h = __floats2half2_rn(sacc[mt][2 * kt][2],     sacc[mt][2 * kt][3]);
            pa[mt][1] = *(uint32_t*)&h;
            h = __floats2half2_rn(sacc[mt][2 * kt + 1][0], sacc[mt][2 * kt + 1][1]);
            pa[mt][2] = *(uint32_t*)&h;
            h = __floats2half2_rn(sacc[mt][2 * kt + 1][2], sacc[mt][2 * kt + 1][3]);
            pa[mt][3] = *(uint32_t*)&h;
        }
        #pragma unroll
        for (int ng = 0; ng < 3; ng++) {
            uint32_t vb[4];
            ldsm_x4t(vb, uV + (uint32_t)(((kt * 16 + lr) * AST + ng * 32 + lc * 8) * 2));
            #pragma unroll
            for (int mt = 0; mt < 2; mt++) {
                mma16816h2(cacc[mt][4 * ng],     pa[mt], vb[0], vb[1]);
                mma16816h2(cacc[mt][4 * ng + 1], pa[mt], vb[2], vb[3]);
            }
            uint32_t vb2[4];
            ldsm_x4t(vb2, uV + (uint32_t)(((kt * 16 + lr) * AST + ng * 32 + 16 + lc * 8) * 2));
            #pragma unroll
            for (int mt = 0; mt < 2; mt++) {
                mma16816h2(cacc[mt][4 * ng + 2], pa[mt], vb2[0], vb2[1]);
                mma16816h2(cacc[mt][4 * ng + 3], pa[mt], vb2[2], vb2[3]);
            }
        }
    }

    #pragma unroll
    for (int mt = 0; mt < 2; mt++) {
        int q0 = m_base + mt * 16 + (lane >> 2);
        #pragma unroll
        for (int rr = 0; rr < 2; rr++) {
            int q = q0 + rr * 8;
            if (q < KQ) {
                float iv = minv[mt][rr];
                size_t ob = ((size_t)b * KQ + q) * D + hh * HD;
                #pragma unroll
                for (int j2 = 0; j2 < 12; j2++) {
                    int d = j2 * 8 + c0;
                    float* c = cacc[mt][j2];
                    __half2 p;
                    p.x = __float2half_rn(c[2 * rr]     * iv);
                    p.y = __float2half_rn(c[2 * rr + 1] * iv);
                    *(__half2*)(ch + ob + d) = p;
                }
            }
        }
    }
}

// ---------------------------------------------------------------------------
// GroupFC with fused final LayerNorm. I (ffn out) now fp16.
// grid = (KQ, 4), 256 threads, 32 batches/block, warp-per-row LN + dot.
// ---------------------------------------------------------------------------
#define GFC_BPB 32
__global__ __launch_bounds__(256)
void groupfc_ln(const float* __restrict__ R, const __half* __restrict__ I,
                const float* __restrict__ g3, const float* __restrict__ be3,
                const float* __restrict__ P, const float* __restrict__ db,
                float* __restrict__ out)
{
    __shared__ float sP[D * GRP];   // 30720 B
    const int k  = blockIdx.x;
    const int b0 = blockIdx.y * GFC_BPB;
    const float* pp = P + (size_t)k * D * GRP;
    for (int i = threadIdx.x; i < D * GRP; i += 256) sP[i] = pp[i];
    __syncthreads();

    const int warp = threadIdx.x >> 5, lane = threadIdx.x & 31;
    #pragma unroll
    for (int bi = 0; bi < GFC_BPB / 8; bi++) {
        int b = b0 + warp + bi * 8;
        size_t row = (size_t)b * KQ + k;
        const float* rp = R + row * D;
        const __half* ip = I + row * D;

        float v[24];
        float s = 0.0f;
        #pragma unroll
        for (int i = 0; i < 24; i++) {
            int c = lane + i * 32;
            v[i] = rp[c] + __half2float(ip[c]);
            s += v[i];
        }
        #pragma unroll
        for (int o = 16; o > 0; o >>= 1) s += __shfl_xor_sync(0xffffffffu, s, o);
        float mean = s * (1.0f / D);
        float vs = 0.0f;
        #pragma unroll
        for (int i = 0; i < 24; i++) { float d = v[i] - mean; vs += d * d; }
        #pragma unroll
        for (int o = 16; o > 0; o >>= 1) vs += __shfl_xor_sync(0xffffffffu, vs, o);
        float inv = rsqrtf(vs * (1.0f / D) + EPS);

        float acc[GRP] = {};
        #pragma unroll
        for (int i = 0; i < 24; i++) {
            int c = lane + i * 32;
            float h = (v[i] - mean) * inv * g3[c] + be3[c];
            const float* q = sP + c * GRP;
            #pragma unroll
            for (int g = 0; g < GRP; g++) acc[g] += h * q[g];
        }
        #pragma unroll
        for (int g = 0; g < GRP; g++)
            #pragma unroll
            for (int o = 16; o > 0; o >>= 1)
                acc[g] += __shfl_xor_sync(0xffffffffu, acc[g], o);
        if (lane < GRP) {
            float val = 0.0f;
            #pragma unroll
            for (int g = 0; g < GRP; g++) if (lane == g) val = acc[g];
            out[(size_t)b * NC + k * GRP + lane] = val + db[k * GRP + lane];
        }
    }
}

// ---------------------------------------------------------------------------
// Host launcher
// ---------------------------------------------------------------------------
extern "C" void kernel_launch(void* const* d_in, const int* in_sizes, int n_in,
                              void* d_out, int out_size)
{
    (void)in_sizes; (void)n_in; (void)out_size;
    const float* x        = (const float*)d_in[0];
    const float* W_embed  = (const float*)d_in[1];
    const float* b_embed  = (const float*)d_in[2];
    const float* query_embed = (const float*)d_in[3];
    const float* wq = (const float*)d_in[4];
    const float* wk = (const float*)d_in[5];
    const float* wv = (const float*)d_in[6];
    const float* bq = (const float*)d_in[7];
    const float* bk = (const float*)d_in[8];
    const float* bv = (const float*)d_in[9];
    const float* wo = (const float*)d_in[10];
    const float* bo = (const float*)d_in[11];
    const float* w1 = (const float*)d_in[12];
    const float* b1 = (const float*)d_in[13];
    const float* w2 = (const float*)d_in[14];
    const float* b2 = (const float*)d_in[15];
    const float* g1 = (const float*)d_in[16];
    const float* be1= (const float*)d_in[17];
    const float* g2 = (const float*)d_in[18];
    const float* be2= (const float*)d_in[19];
    const float* g3 = (const float*)d_in[20];
    const float* be3= (const float*)d_in[21];
    const float* dup_pool = (const float*)d_in[22];
    const float* dup_bias = (const float*)d_in[23];
    float* out = (float*)d_out;

    __half *xT, *memh, *ctxh, *t2h, *h1h, *tlnh, *qh, *kvh, *tmph, *h2h;
    __half *We, *wqc, *wkvc, *woc, *w1c, *w2c;
    float *bkv, *tln, *tgt2;
    cudaGetSymbolAddress((void**)&xT,   g_xT);
    cudaGetSymbolAddress((void**)&memh, g_memh);
    cudaGetSymbolAddress((void**)&ctxh, g_ctxh);
    cudaGetSymbolAddress((void**)&t2h,  g_t2h);
    cudaGetSymbolAddress((void**)&h1h,  g_h1h);
    cudaGetSymbolAddress((void**)&tlnh, g_tlnh);
    cudaGetSymbolAddress((void**)&qh,   g_qh);
    cudaGetSymbolAddress((void**)&kvh,  g_kvh);
    cudaGetSymbolAddress((void**)&tmph, g_tmph);
    cudaGetSymbolAddress((void**)&h2h,  g_h2h);
    cudaGetSymbolAddress((void**)&We,   g_We);
    cudaGetSymbolAddress((void**)&wqc,  g_wq);
    cudaGetSymbolAddress((void**)&wkvc, g_wkv);
    cudaGetSymbolAddress((void**)&woc,  g_wo);
    cudaGetSymbolAddress((void**)&w1c,  g_w1);
    cudaGetSymbolAddress((void**)&w2c,  g_w2);
    cudaGetSymbolAddress((void**)&bkv,  g_bkv);
    cudaGetSymbolAddress((void**)&tln,  g_tgtln);
    cudaGetSymbolAddress((void**)&tgt2, g_tgt2);

    const int BKQ = BATCH * KQ;     // 12800
    const int BS  = BATCH * SEQ;    // 6272

    static bool attr_set = false;
    if (!attr_set) {
        cudaFuncSetAttribute(mma_gemm<true,  false, true >, cudaFuncAttributeMaxDynamicSharedMemorySize, SMEM_GEMM);
        cudaFuncSetAttribute(mma_gemm<false, false, true >, cudaFuncAttributeMaxDynamicSharedMemorySize, SMEM_GEMM);
        cudaFuncSetAttribute(mma_gemm_kvq, cudaFuncAttributeMaxDynamicSharedMemorySize, SMEM_GEMM);
        cudaFuncSetAttribute(attn_mma, cudaFuncAttributeMaxDynamicSharedMemorySize, SMEM_ATTN);
        attr_set = true;
    }

    // 0) merged preprocessing (1 launch)
    preproc<<<PP_GRID, 256>>>(x, xT,
        W_embed, We, wo, woc, w1, w1c, w2, w2c, wq, wqc,
        wk, wv, bk, bv, wkvc, bkv,
        query_embed, g1, be1, tln, tlnh);

    // 1) embed: mem = relu(xT @ W_embed + b_embed) -> fp16   (6272 x 768 x 2048)
    mma_gemm<true, false, true><<<dim3(D / TBN, BS / TBM), 256, SMEM_GEMM>>>(
        xT, We, b_embed, nullptr, memh, BS, D, FDIM);

    // 2+3) fused K|V projection (6272x1536x768) + q projection (128x768x768)
    mma_gemm_kvq<<<dim3(DKV / TBN, BS / TBM + 1), 256, SMEM_GEMM>>>(
        memh, wkvc, bkv, kvh, tlnh, wqc, bq, qh);

    // 4) attention (tensor-core flash-style) -> ctx fp16
    attn_mma<<<dim3(NHEAD, BATCH), 128, SMEM_ATTN>>>(qh, kvh, ctxh);

    // 5) attn_out = ctx @ wo + bo -> fp16
    mma_gemm<false, false, true><<<dim3(D / TBN, BKQ / TBM), 256, SMEM_GEMM>>>(
        ctxh, woc, bo, nullptr, tmph, BKQ, D, D);

    // 6) tgt2 = LN(tgt_ln + attn_out) -> fp32 + fp16 (warp-per-row)
    ln_residual_w<<<BKQ / 8, 256>>>(tln, tmph, g2, be2, tgt2, t2h);

    // 7) FFN
    mma_gemm<true, false, true><<<dim3(FF / TBN, BKQ / TBM), 256, SMEM_GEMM>>>(
        t2h, w1c, b1, nullptr, h1h, BKQ, FF, D);
    mma_gemm<false, false, true><<<dim3(D / TBN, BKQ / TBM), 256, SMEM_GEMM>>>(
        h1h, w2c, b2, nullptr, h2h, BKQ, D, FF);

    // 8+9) fused LN + group FC -> logits
    groupfc_ln<<<dim3(KQ, 4), 256>>>(tgt2, h2h, g3, be3, dup_pool, dup_bias, out);
}

// round 16
// speedup vs baseline: 1.4540x; 1.4540x over previous
#include <cuda_runtime.h>
#include <cuda_fp16.h>
#include <math.h>
#include <stdint.h>

// ---------------------------------------------------------------------------
// Problem constants
// ---------------------------------------------------------------------------
#define BATCH 128
#define SEQ   49
#define FDIM  2048
#define D     768
#define KQ    100
#define NHEAD 8
#define HD    96
#define FF    2048
#define NC    1000
#define GRP   10
#define EPS   1e-5f
#define DKV   1536      // concatenated K|V width

// ---------------------------------------------------------------------------
// Scratch (static device globals; no allocation allowed)
// ---------------------------------------------------------------------------
__device__ __half g_xT  [BATCH * SEQ * FDIM];
__device__ __half g_memh[BATCH * SEQ * D];
__device__ __half g_ctxh[BATCH * KQ * D];
__device__ __half g_t2h [BATCH * KQ * D];
__device__ __half g_h1h [BATCH * KQ * FF];
__device__ __half g_tlnh[128 * D];             // fp16 tgt_ln padded to 128 rows
__device__ __half g_qh  [128 * D];             // fp16 q projection
__device__ __half g_kvh [BATCH * SEQ * DKV];   // fp16 K|V fused projection
// fp16 weights ([K, N] row-major); wkv = concat(wk, wv) along N
__device__ __half g_We [FDIM * D];
__device__ __half g_wq [D * D];
__device__ __half g_wkv[D * DKV];
__device__ __half g_wo [D * D];
__device__ __half g_w1 [D * FF];
__device__ __half g_w2 [FF * D];
__device__ float  g_bkv[DKV];
// fp32 buffers
__device__ float g_tgtln[KQ * D];
__device__ float g_tmp  [BATCH * KQ * D];
__device__ float g_tgt2 [BATCH * KQ * D];
__device__ float g_h2   [BATCH * KQ * D];

// ---------------------------------------------------------------------------
// PTX helpers
// ---------------------------------------------------------------------------
__device__ __forceinline__ uint32_t smem_u32(const void* p) {
    return (uint32_t)__cvta_generic_to_shared(p);
}
__device__ __forceinline__ void ldsm_x4(uint32_t* d, uint32_t addr) {
    asm volatile("ldmatrix.sync.aligned.m8n8.x4.shared.b16 {%0,%1,%2,%3}, [%4];"
        : "=r"(d[0]), "=r"(d[1]), "=r"(d[2]), "=r"(d[3]) : "r"(addr));
}
__device__ __forceinline__ void ldsm_x4t(uint32_t* d, uint32_t addr) {
    asm volatile("ldmatrix.sync.aligned.m8n8.x4.trans.shared.b16 {%0,%1,%2,%3}, [%4];"
        : "=r"(d[0]), "=r"(d[1]), "=r"(d[2]), "=r"(d[3]) : "r"(addr));
}
__device__ __forceinline__ void mma16816h(float* c, const uint32_t* a, const uint32_t* b) {
    asm volatile("mma.sync.aligned.m16n8k16.row.col.f32.f16.f16.f32 "
        "{%0,%1,%2,%3}, {%4,%5,%6,%7}, {%8,%9}, {%0,%1,%2,%3};"
        : "+f"(c[0]), "+f"(c[1]), "+f"(c[2]), "+f"(c[3])
        : "r"(a[0]), "r"(a[1]), "r"(a[2]), "r"(a[3]), "r"(b[0]), "r"(b[1]));
}
__device__ __forceinline__ void mma16816h2(float* c, const uint32_t* a,
                                           uint32_t b0, uint32_t b1) {
    asm volatile("mma.sync.aligned.m16n8k16.row.col.f32.f16.f16.f32 "
        "{%0,%1,%2,%3}, {%4,%5,%6,%7}, {%8,%9}, {%0,%1,%2,%3};"
        : "+f"(c[0]), "+f"(c[1]), "+f"(c[2]), "+f"(c[3])
        : "r"(a[0]), "r"(a[1]), "r"(a[2]), "r"(a[3]), "r"(b0), "r"(b1));
}
__device__ __forceinline__ void cp_async16(uint32_t dst, const void* src) {
    asm volatile("cp.async.cg.shared.global [%0], [%1], 16;"
        :: "r"(dst), "l"(src) : "memory");
}
__device__ __forceinline__ void cp_commit() {
    asm volatile("cp.async.commit_group;" ::: "memory");
}
template<int N_>
__device__ __forceinline__ void cp_wait() {
    asm volatile("cp.async.wait_group %0;" :: "n"(N_) : "memory");
}

// ---------------------------------------------------------------------------
// Tensor-core GEMM tile (R7/R10-proven config, as device function):
// C = A_fp16 @ B_fp16 + bias. CTA tile 128x128, BK=32, 256 threads
// (2Mx4N warps, warp tile 64x32), 4-stage cp.async pipeline, one
// __syncthreads per k-iter, load issued between the two k16 halves.
// 2 CTAs/SM. N%128==0, K%32==0.
// ---------------------------------------------------------------------------
#define TBM 128
#define TBN 128
#define TBK 32
#define NSTG 4
#define A_STRIDE (TBK + 8)      // 40 halfs
#define B_STRIDE (TBN + 8)      // 136 halfs
#define A_BUF (TBM * A_STRIDE)  // 5120 halfs
#define B_BUF (TBK * B_STRIDE)  // 4352 halfs
#define STAGE_HALFS (A_BUF + B_BUF)              // 9472
#define SMEM_GEMM (NSTG * STAGE_HALFS * 2)       // 75776 B

template<bool RELU, bool WF32, bool WHALF>
__device__ __forceinline__
void gemm_tile(const __half* __restrict__ A, const __half* __restrict__ B,
               const float* __restrict__ bias,
               float* __restrict__ Cf, __half* __restrict__ Ch,
               int N, int K, int m0, int n0, unsigned char* smem_raw)
{
    __half* sA = (__half*)smem_raw;               // [NSTG][A_BUF]
    __half* sB = sA + NSTG * A_BUF;               // [NSTG][B_BUF]

    const int tid  = threadIdx.x;
    const int lane = tid & 31;
    const int warp = tid >> 5;
    const int m_base = (warp & 1) * 64;
    const int n_base = (warp >> 1) * 32;

    const int ar = tid >> 2,  ac = (tid & 3) * 8;    // A: rows ar, ar+64
    const int br = tid >> 4,  bc = (tid & 15) * 8;   // B: rows br, br+16

    const uint32_t uA = smem_u32(sA);
    const uint32_t uB = smem_u32(sB);

    float acc[4][4][4];
    #pragma unroll
    for (int i = 0; i < 4; i++)
        #pragma unroll
        for (int j = 0; j < 4; j++)
            #pragma unroll
            for (int k = 0; k < 4; k++) acc[i][j][k] = 0.0f;

    auto load_async = [&](int it, int buf) {
        const int k0 = it * TBK;
        uint32_t dA = uA + (uint32_t)((buf * A_BUF + ar * A_STRIDE + ac) * 2);
        const __half* gA = A + (size_t)(m0 + ar) * K + k0 + ac;
        cp_async16(dA, gA);
        cp_async16(dA + (uint32_t)(64 * A_STRIDE * 2), gA + (size_t)64 * K);
        uint32_t dB = uB + (uint32_t)((buf * B_BUF + br * B_STRIDE + bc) * 2);
        const __half* gB = B + (size_t)(k0 + br) * N + n0 + bc;
        cp_async16(dB, gB);
        cp_async16(dB + (uint32_t)(16 * B_STRIDE * 2), gB + (size_t)16 * N);
    };

    const int lr = lane & 15;
    const int lc = lane >> 4;

    auto compute_k = [&](int buf, int kk) {
        uint32_t a[4][4], b[2][4];
        #pragma unroll
        for (int mt = 0; mt < 4; mt++) {
            uint32_t off = (uint32_t)((buf * A_BUF +
                (m_base + mt * 16 + lr) * A_STRIDE + kk + lc * 8) * 2);
            ldsm_x4(a[mt], uA + off);
        }
        #pragma unroll
        for (int ng = 0; ng < 2; ng++) {
            uint32_t off = (uint32_t)((buf * B_BUF +
                (kk + lr) * B_STRIDE + n_base + ng * 16 + lc * 8) * 2);
            ldsm_x4t(b[ng], uB + off);
        }
        #pragma unroll
        for (int mt = 0; mt < 4; mt++)
            #pragma unroll
            for (int ng = 0; ng < 2; ng++)
                #pragma unroll
                for (int h = 0; h < 2; h++)
                    mma16816h(acc[mt][ng * 2 + h], a[mt], &b[ng][2 * h]);
    };

    const int niter = K / TBK;
    #pragma unroll
    for (int s = 0; s < NSTG - 1; s++) {
        if (s < niter) load_async(s, s);
        cp_commit();
    }
    int buf = 0;
    for (int it = 0; it < niter; it++) {
        cp_wait<NSTG - 2>();
        __syncthreads();
        compute_k(buf, 0);
        const int nx = it + NSTG - 1;
        if (nx < niter) {
            int nbuf = buf - 1; if (nbuf < 0) nbuf += NSTG;
            load_async(nx, nbuf);
        }
        cp_commit();
        compute_k(buf, 16);
        if (++buf == NSTG) buf = 0;
    }

    // epilogue
    #pragma unroll
    for (int mt = 0; mt < 4; mt++) {
        int r0 = m0 + m_base + mt * 16 + (lane >> 2);
        #pragma unroll
        for (int j = 0; j < 4; j++) {
            int col = n0 + n_base + j * 8 + (lane & 3) * 2;
            float bx = bias[col], by = bias[col + 1];
            float* c = acc[mt][j];
            float v00 = c[0] + bx, v01 = c[1] + by;
            float v10 = c[2] + bx, v11 = c[3] + by;
            if (RELU) {
                v00 = fmaxf(v00, 0.f); v01 = fmaxf(v01, 0.f);
                v10 = fmaxf(v10, 0.f); v11 = fmaxf(v11, 0.f);
            }
            if (WF32) {
                *(float2*)(Cf + (size_t)r0 * N + col)       = make_float2(v00, v01);
                *(float2*)(Cf + (size_t)(r0 + 8) * N + col) = make_float2(v10, v11);
            }
            if (WHALF) {
                __half2 p0; p0.x = __float2half_rn(v00); p0.y = __float2half_rn(v01);
                __half2 p1; p1.x = __float2half_rn(v10); p1.y = __float2half_rn(v11);
                *(__half2*)(Ch + (size_t)r0 * N + col)       = p0;
                *(__half2*)(Ch + (size_t)(r0 + 8) * N + col) = p1;
            }
        }
    }
}

template<bool RELU, bool WF32, bool WHALF>
__global__ __launch_bounds__(256, 2)
void mma_gemm(const __half* __restrict__ A, const __half* __restrict__ B,
              const float* __restrict__ bias,
              float* __restrict__ Cf, __half* __restrict__ Ch,
              int M, int N, int K)
{
    extern __shared__ __align__(16) unsigned char smem_raw[];
    (void)M;
    gemm_tile<RELU, WF32, WHALF>(A, B, bias, Cf, Ch, N, K,
                                 blockIdx.y * TBM, blockIdx.x * TBN, smem_raw);
}

// Fused KV-projection + q-projection GEMM.
// grid = (12, 50): rows 0..48 = KV tiles (N=DKV), row 49 = q tiles (N=D, 6 used)
__global__ __launch_bounds__(256, 2)
void mma_gemm_kvq(const __half* __restrict__ Akv, const __half* __restrict__ Bkv,
                  const float* __restrict__ bkv, __half* __restrict__ Ckv,
                  const __half* __restrict__ Aq, const __half* __restrict__ Bq,
                  const float* __restrict__ bq, __half* __restrict__ Cq)
{
    extern __shared__ __align__(16) unsigned char smem_raw[];
    if (blockIdx.y < 49) {
        gemm_tile<false, false, true>(Akv, Bkv, bkv, nullptr, Ckv, DKV, D,
                                      blockIdx.y * TBM, blockIdx.x * TBN, smem_raw);
    } else {
        if (blockIdx.x >= D / TBN) return;
        gemm_tile<false, false, true>(Aq, Bq, bq, nullptr, Cq, D, D,
                                      0, blockIdx.x * TBN, smem_raw);
    }
}

// ---------------------------------------------------------------------------
// Transpose + fp16 convert: x (B, FDIM, SEQ) -> A (B*SEQ, FDIM)
// ---------------------------------------------------------------------------
__global__ __launch_bounds__(256)
void xT_cvt(const float* __restrict__ x, __half* __restrict__ o)
{
    __shared__ float t[32][33];
    int b = blockIdx.z;
    int f0 = blockIdx.x * 32, s0 = blockIdx.y * 32;
    const float* xb = x + (size_t)b * FDIM * SEQ;
    int tx = threadIdx.x, ty = threadIdx.y;
    #pragma unroll
    for (int i = ty; i < 32; i += 8) {
        int s = s0 + tx;
        t[i][tx] = (s < SEQ) ? xb[(size_t)(f0 + i) * SEQ + s] : 0.f;
    }
    __syncthreads();
    #pragma unroll
    for (int i = ty; i < 32; i += 8) {
        int s = s0 + i, f = f0 + tx;
        if (s < SEQ)
            o[((size_t)b * SEQ + s) * FDIM + f] = __float2half_rn(t[tx][i]);
    }
}

// ---------------------------------------------------------------------------
// Merged fp32 -> fp16 weight conversion: 5 jobs in one launch (blockIdx.y)
// ---------------------------------------------------------------------------
__global__ __launch_bounds__(256)
void cvt_f16_multi(const float* __restrict__ s0, __half* __restrict__ d0, int n0,
                   const float* __restrict__ s1, __half* __restrict__ d1, int n1,
                   const float* __restrict__ s2, __half* __restrict__ d2, int n2,
                   const float* __restrict__ s3, __half* __restrict__ d3, int n3,
                   const float* __restrict__ s4, __half* __restrict__ d4, int n4)
{
    const float* s; __half* d; int n;
    switch (blockIdx.y) {
        case 0: s = s0; d = d0; n = n0; break;
        case 1: s = s1; d = d1; n = n1; break;
        case 2: s = s2; d = d2; n = n2; break;
        case 3: s = s3; d = d3; n = n3; break;
        default: s = s4; d = d4; n = n4; break;
    }
    for (int i = blockIdx.x * 256 + threadIdx.x; i < n; i += gridDim.x * 256) {
        float4 v = ((const float4*)s)[i];
        __half2 h0, h1;
        h0.x = __float2half_rn(v.x); h0.y = __float2half_rn(v.y);
        h1.x = __float2half_rn(v.z); h1.y = __float2half_rn(v.w);
        ((__half2*)d)[i * 2]     = h0;
        ((__half2*)d)[i * 2 + 1] = h1;
    }
}

// ---------------------------------------------------------------------------
// wk|wv -> concatenated fp16 wkv [D, 1536] + bkv = concat(bk, bv)
// ---------------------------------------------------------------------------
__global__ __launch_bounds__(256)
void cvt_wkv(const float* __restrict__ wk, const float* __restrict__ wv,
             const float* __restrict__ bk, const float* __restrict__ bv,
             __half* __restrict__ o, float* __restrict__ ob)
{
    int gt = blockIdx.x * 256 + threadIdx.x;
    if (gt < DKV) ob[gt] = (gt < D) ? bk[gt] : bv[gt - D];
    if (gt < D * DKV / 4) {
        int k = gt / (DKV / 4);
        int c4 = gt - k * (DKV / 4);
        int n = c4 * 4;
        const float* src = (n < D) ? (wk + (size_t)k * D + n)
                                   : (wv + (size_t)k * D + n - D);
        float4 v = *(const float4*)src;
        __half2 h0, h1;
        h0.x = __float2half_rn(v.x); h0.y = __float2half_rn(v.y);
        h1.x = __float2half_rn(v.z); h1.y = __float2half_rn(v.w);
        ((__half2*)o)[gt * 2]     = h0;
        ((__half2*)o)[gt * 2 + 1] = h1;
    }
}

// ---------------------------------------------------------------------------
// Block reduction helper
// ---------------------------------------------------------------------------
__device__ __forceinline__ float block_sum(float v, float* sred) {
    int lane = threadIdx.x & 31, w = threadIdx.x >> 5;
    #pragma unroll
    for (int o = 16; o > 0; o >>= 1) v += __shfl_down_sync(0xffffffffu, v, o);
    if (lane == 0) sred[w] = v;
    __syncthreads();
    float s = (threadIdx.x < 8) ? sred[threadIdx.x] : 0.0f;
    if (w == 0) {
        #pragma unroll
        for (int o = 4; o > 0; o >>= 1) s += __shfl_down_sync(0xffffffffu, s, o);
        if (lane == 0) sred[0] = s;
    }
    __syncthreads();
    float r = sred[0];
    __syncthreads();
    return r;
}

// ---------------------------------------------------------------------------
// tgt_ln = layernorm(2 * query_embed) * g1 + be1
// grid = 128 rows: rows >= 100 write fp16 zeros (padding for the q GEMM).
// ---------------------------------------------------------------------------
__global__ __launch_bounds__(256)
void ln_query(const float* __restrict__ qe, const float* __restrict__ g,
              const float* __restrict__ be, float* __restrict__ out,
              __half* __restrict__ oh)
{
    __shared__ float sred[8];
    int r = blockIdx.x, t = threadIdx.x;
    if (r >= KQ) {
        #pragma unroll
        for (int i = 0; i < 3; i++)
            oh[(size_t)r * D + t + i * 256] = __float2half_rn(0.0f);
        return;
    }
    float v[3];
    float s = 0.0f;
    #pragma unroll
    for (int i = 0; i < 3; i++) { v[i] = 2.0f * qe[(size_t)r * D + t + i * 256]; s += v[i]; }
    float mean = block_sum(s, sred) * (1.0f / D);
    float vs = 0.0f;
    #pragma unroll
    for (int i = 0; i < 3; i++) { float d = v[i] - mean; vs += d * d; }
    float var = block_sum(vs, sred) * (1.0f / D);
    float inv = rsqrtf(var + EPS);
    #pragma unroll
    for (int i = 0; i < 3; i++) {
        int c = t + i * 256;
        float o = (v[i] - mean) * inv * g[c] + be[c];
        out[(size_t)r * D + c] = o;
        oh[(size_t)r * D + c] = __float2half_rn(o);
    }
}

// ---------------------------------------------------------------------------
// out = LN(res[r % KQ] + inp[r]) ; warp-per-row, 8 rows/block. grid = rows/8.
// ---------------------------------------------------------------------------
__global__ __launch_bounds__(256)
void ln_residual_w(const float* __restrict__ res, const float* __restrict__ inp,
                   const float* __restrict__ g, const float* __restrict__ be,
                   float* __restrict__ out, __half* __restrict__ oh)
{
    const int warp = threadIdx.x >> 5, lane = threadIdx.x & 31;
    long r = (long)blockIdx.x * 8 + warp;
    long rr = r % KQ;
    const float* rp = res + rr * D;
    const float* ip = inp + r * D;

    float v[24];
    float s = 0.0f;
    #pragma unroll
    for (int i = 0; i < 24; i++) {
        int c = lane + i * 32;
        v[i] = rp[c] + ip[c];
        s += v[i];
    }
    #pragma unroll
    for (int o = 16; o > 0; o >>= 1) s += __shfl_xor_sync(0xffffffffu, s, o);
    float mean = s * (1.0f / D);
    float vs = 0.0f;
    #pragma unroll
    for (int i = 0; i < 24; i++) { float d = v[i] - mean; vs += d * d; }
    #pragma unroll
    for (int o = 16; o > 0; o >>= 1) vs += __shfl_xor_sync(0xffffffffu, vs, o);
    float inv = rsqrtf(vs * (1.0f / D) + EPS);
    #pragma unroll
    for (int i = 0; i < 24; i++) {
        int c = lane + i * 32;
        float o = (v[i] - mean) * inv * g[c] + be[c];
        out[r * D + c] = o;
        oh[r * D + c] = __float2half_rn(o);
    }
}

// ---------------------------------------------------------------------------
// Tensor-core cross attention, 8 warps (one 16-row m-tile per warp).
// grid=(NHEAD, BATCH), 256 threads. Same per-row math as the R13 kernel.
// Dynamic smem: Q[128x104] + K[64x104] + V[64x104] fp16 = 53248 B.
// ---------------------------------------------------------------------------
#define AST 104                                // smem row stride (halfs)
#define SMEM_ATTN ((128 + 64 + 64) * AST * 2)  // 53248 B

__global__ __launch_bounds__(256)
void attn_mma(const __half* __restrict__ Q, const __half* __restrict__ KV,
              __half* __restrict__ ch)
{
    extern __shared__ __align__(16) __half smA[];
    __half* Qs = smA;                 // [128][AST]
    __half* Ks = Qs + 128 * AST;      // [64][AST] (rows >= SEQ zero)
    __half* Vs = Ks + 64 * AST;       // [64][AST] (rows >= SEQ zero)
    const int hh = blockIdx.x, b = blockIdx.y;
    const int t = threadIdx.x;
    const int lane = t & 31, warp = t >> 5;

    for (int idx = t; idx < 128 * 48; idx += 256) {
        int r = idx / 48, d2 = idx - r * 48;
        ((__half2*)(Qs + r * AST))[d2] =
            *(const __half2*)(Q + (size_t)r * D + hh * HD + 2 * d2);
    }
    for (int idx = t; idx < 64 * 48; idx += 256) {
        int s = idx / 48, d2 = idx - s * 48;
        __half2 kk2, vv2;
        if (s < SEQ) {
            size_t off = ((size_t)b * SEQ + s) * DKV + hh * HD + 2 * d2;
            kk2 = *(const __half2*)(KV + off);
            vv2 = *(const __half2*)(KV + off + D);
        } else {
            kk2.x = __float2half_rn(0.f); kk2.y = kk2.x;
            vv2 = kk2;
        }
        ((__half2*)(Ks + s * AST))[d2] = kk2;
        ((__half2*)(Vs + s * AST))[d2] = vv2;
    }
    __syncthreads();

    const int lr = lane & 15, lc = lane >> 4;
    const int m_base = warp * 16;
    const uint32_t uQ = smem_u32(Qs), uK = smem_u32(Ks), uV = smem_u32(Vs);

    // ---- S = Q K^T : sacc[j][*], j = n8 tile 0..7 (cols 0..63) ----
    float sacc[8][4];
    #pragma unroll
    for (int j = 0; j < 8; j++)
        #pragma unroll
        for (int k = 0; k < 4; k++) sacc[j][k] = 0.0f;

    #pragma unroll
    for (int kk = 0; kk < HD; kk += 16) {
        uint32_t a[4];
        ldsm_x4(a, uQ + (uint32_t)(((m_base + lr) * AST + kk + lc * 8) * 2));
        uint32_t kb[4][4];
        #pragma unroll
        for (int ng = 0; ng < 4; ng++)
            ldsm_x4(kb[ng], uK + (uint32_t)(((ng * 16 + lr) * AST + kk + lc * 8) * 2));
        #pragma unroll
        for (int ng = 0; ng < 4; ng++) {
            // K stored [n][k]: frag pairs (r0,r2) and (r1,r3)
            mma16816h2(sacc[2 * ng],     a, kb[ng][0], kb[ng][2]);
            mma16816h2(sacc[2 * ng + 1], a, kb[ng][1], kb[ng][3]);
        }
    }

    // ---- fragment softmax (cols >= SEQ masked) ----
    const float scale = 0.102062072615966f;   // 1/sqrt(96)
    const int c0 = (lane & 3) * 2;
    float minv[2];
    {
        float m0 = -1e30f, m1 = -1e30f;
        #pragma unroll
        for (int j = 0; j < 8; j++) {
            int n = j * 8 + c0;
            float* c = sacc[j];
            c[0] = (n     < SEQ) ? c[0] * scale : -1e30f;
            c[1] = (n + 1 < SEQ) ? c[1] * scale : -1e30f;
            c[2] = (n     < SEQ) ? c[2] * scale : -1e30f;
            c[3] = (n + 1 < SEQ) ? c[3] * scale : -1e30f;
            m0 = fmaxf(m0, fmaxf(c[0], c[1]));
            m1 = fmaxf(m1, fmaxf(c[2], c[3]));
        }
        m0 = fmaxf(m0, __shfl_xor_sync(0xffffffffu, m0, 1));
        m0 = fmaxf(m0, __shfl_xor_sync(0xffffffffu, m0, 2));
        m1 = fmaxf(m1, __shfl_xor_sync(0xffffffffu, m1, 1));
        m1 = fmaxf(m1, __shfl_xor_sync(0xffffffffu, m1, 2));
        float l0 = 0.f, l1 = 0.f;
        #pragma unroll
        for (int j = 0; j < 8; j++) {
            float* c = sacc[j];
            c[0] = __expf(c[0] - m0); c[1] = __expf(c[1] - m0);
            c[2] = __expf(c[2] - m1); c[3] = __expf(c[3] - m1);
            l0 += c[0] + c[1];
            l1 += c[2] + c[3];
        }
        l0 += __shfl_xor_sync(0xffffffffu, l0, 1);
        l0 += __shfl_xor_sync(0xffffffffu, l0, 2);
        l1 += __shfl_xor_sync(0xffffffffu, l1, 1);
        l1 += __shfl_xor_sync(0xffffffffu, l1, 2);
        minv[0] = 1.0f / l0;
        minv[1] = 1.0f / l1;
    }

    // ---- ctx = P V : cacc[j2][*], j2 = n8 tile 0..11 (d = 0..95) ----
    float cacc[12][4];
    #pragma unroll
    for (int j = 0; j < 12; j++)
        #pragma unroll
        for (int k = 0; k < 4; k++) cacc[j][k] = 0.0f;

    #pragma unroll
    for (int kt = 0; kt < 4; kt++) {          // s dim 64 = 4 x k16
        uint32_t pa[4];
        {
            __half2 h;
            h = __floats2half2_rn(sacc[2 * kt][0],     sacc[2 * kt][1]);
            pa[0] = *(uint32_t*)&h;
            h = __floats2half2_rn(sacc[2 * kt][2],     sacc[2 * kt][3]);
            pa[1] = *(uint32_t*)&h;
            h = __floats2half2_rn(sacc[2 * kt + 1][0], sacc[2 * kt + 1][1]);
            pa[2] = *(uint32_t*)&h;
            h = __floats2half2_rn(sacc[2 * kt + 1][2], sacc[2 * kt + 1][3]);
            pa[3] = *(uint32_t*)&h;
        }
        #pragma unroll
        for (int ng = 0; ng < 3; ng++) {      // d dim 96 = 3 x 32
            uint32_t vb[4];
            ldsm_x4t(vb, uV + (uint32_t)(((kt * 16 + lr) * AST + ng * 32 + lc * 8) * 2));
            mma16816h2(cacc[4 * ng],     pa, vb[0], vb[1]);
            mma16816h2(cacc[4 * ng + 1], pa, vb[2], vb[3]);
            uint32_t vb2[4];
            ldsm_x4t(vb2, uV + (uint32_t)(((kt * 16 + lr) * AST + ng * 32 + 16 + lc * 8) * 2));
            mma16816h2(cacc[4 * ng + 2], pa, vb2[0], vb2[1]);
            mma16816h2(cacc[4 * ng + 3], pa, vb2[2], vb2[3]);
        }
    }

    // ---- store ctx rows < KQ, scaled by 1/l ----
    {
        int q0 = m_base + (lane >> 2);
        #pragma unroll
        for (int rr = 0; rr < 2; rr++) {
            int q = q0 + rr * 8;
            if (q < KQ) {
                float iv = minv[rr];
                size_t ob = ((size_t)b * KQ + q) * D + hh * HD;
                #pragma unroll
                for (int j2 = 0; j2 < 12; j2++) {
                    int d = j2 * 8 + c0;
                    float* c = cacc[j2];
                    __half2 p;
                    p.x = __float2half_rn(c[2 * rr]     * iv);
                    p.y = __float2half_rn(c[2 * rr + 1] * iv);
                    *(__half2*)(ch + ob + d) = p;
                }
            }
        }
    }
}

// ---------------------------------------------------------------------------
// GroupFC with fused final LayerNorm.
// grid = (KQ, 4), 256 threads, 32 batches/block, warp-per-row LN + dot.
// ---------------------------------------------------------------------------
#define GFC_BPB 32
__global__ __launch_bounds__(256)
void groupfc_ln(const float* __restrict__ R, const float* __restrict__ I,
                const float* __restrict__ g3, const float* __restrict__ be3,
                const float* __restrict__ P, const float* __restrict__ db,
                float* __restrict__ out)
{
    __shared__ float sP[D * GRP];   // 30720 B
    const int k  = blockIdx.x;
    const int b0 = blockIdx.y * GFC_BPB;
    const float* pp = P + (size_t)k * D * GRP;
    for (int i = threadIdx.x; i < D * GRP; i += 256) sP[i] = pp[i];
    __syncthreads();

    const int warp = threadIdx.x >> 5, lane = threadIdx.x & 31;
    #pragma unroll
    for (int bi = 0; bi < GFC_BPB / 8; bi++) {
        int b = b0 + warp + bi * 8;
        size_t row = (size_t)b * KQ + k;
        const float* rp = R + row * D;
        const float* ip = I + row * D;

        float v[24];
        float s = 0.0f;
        #pragma unroll
        for (int i = 0; i < 24; i++) {
            int c = lane + i * 32;
            v[i] = rp[c] + ip[c];
            s += v[i];
        }
        #pragma unroll
        for (int o = 16; o > 0; o >>= 1) s += __shfl_xor_sync(0xffffffffu, s, o);
        float mean = s * (1.0f / D);
        float vs = 0.0f;
        #pragma unroll
        for (int i = 0; i < 24; i++) { float d = v[i] - mean; vs += d * d; }
        #pragma unroll
        for (int o = 16; o > 0; o >>= 1) vs += __shfl_xor_sync(0xffffffffu, vs, o);
        float inv = rsqrtf(vs * (1.0f / D) + EPS);

        float acc[GRP] = {};
        #pragma unroll
        for (int i = 0; i < 24; i++) {
            int c = lane + i * 32;
            float h = (v[i] - mean) * inv * g3[c] + be3[c];
            const float* q = sP + c * GRP;
            #pragma unroll
            for (int g = 0; g < GRP; g++) acc[g] += h * q[g];
        }
        #pragma unroll
        for (int g = 0; g < GRP; g++)
            #pragma unroll
            for (int o = 16; o > 0; o >>= 1)
                acc[g] += __shfl_xor_sync(0xffffffffu, acc[g], o);
        if (lane < GRP) {
            float val = 0.0f;
            #pragma unroll
            for (int g = 0; g < GRP; g++) if (lane == g) val = acc[g];
            out[(size_t)b * NC + k * GRP + lane] = val + db[k * GRP + lane];
        }
    }
}

// ---------------------------------------------------------------------------
// Host launcher
// ---------------------------------------------------------------------------
extern "C" void kernel_launch(void* const* d_in, const int* in_sizes, int n_in,
                              void* d_out, int out_size)
{
    (void)in_sizes; (void)n_in; (void)out_size;
    const float* x        = (const float*)d_in[0];
    const float* W_embed  = (const float*)d_in[1];
    const float* b_embed  = (const float*)d_in[2];
    const float* query_embed = (const float*)d_in[3];
    const float* wq = (const float*)d_in[4];
    const float* wk = (const float*)d_in[5];
    const float* wv = (const float*)d_in[6];
    const float* bq = (const float*)d_in[7];
    const float* bk = (const float*)d_in[8];
    const float* bv = (const float*)d_in[9];
    const float* wo = (const float*)d_in[10];
    const float* bo = (const float*)d_in[11];
    const float* w1 = (const float*)d_in[12];
    const float* b1 = (const float*)d_in[13];
    const float* w2 = (const float*)d_in[14];
    const float* b2 = (const float*)d_in[15];
    const float* g1 = (const float*)d_in[16];
    const float* be1= (const float*)d_in[17];
    const float* g2 = (const float*)d_in[18];
    const float* be2= (const float*)d_in[19];
    const float* g3 = (const float*)d_in[20];
    const float* be3= (const float*)d_in[21];
    const float* dup_pool = (const float*)d_in[22];
    const float* dup_bias = (const float*)d_in[23];
    float* out = (float*)d_out;

    __half *xT, *memh, *ctxh, *t2h, *h1h, *tlnh, *qh, *kvh;
    __half *We, *wqc, *wkvc, *woc, *w1c, *w2c;
    float *bkv, *tln, *tmp, *tgt2, *h2;
    cudaGetSymbolAddress((void**)&xT,   g_xT);
    cudaGetSymbolAddress((void**)&memh, g_memh);
    cudaGetSymbolAddress((void**)&ctxh, g_ctxh);
    cudaGetSymbolAddress((void**)&t2h,  g_t2h);
    cudaGetSymbolAddress((void**)&h1h,  g_h1h);
    cudaGetSymbolAddress((void**)&tlnh, g_tlnh);
    cudaGetSymbolAddress((void**)&qh,   g_qh);
    cudaGetSymbolAddress((void**)&kvh,  g_kvh);
    cudaGetSymbolAddress((void**)&We,   g_We);
    cudaGetSymbolAddress((void**)&wqc,  g_wq);
    cudaGetSymbolAddress((void**)&wkvc, g_wkv);
    cudaGetSymbolAddress((void**)&woc,  g_wo);
    cudaGetSymbolAddress((void**)&w1c,  g_w1);
    cudaGetSymbolAddress((void**)&w2c,  g_w2);
    cudaGetSymbolAddress((void**)&bkv,  g_bkv);
    cudaGetSymbolAddress((void**)&tln,  g_tgtln);
    cudaGetSymbolAddress((void**)&tmp,  g_tmp);
    cudaGetSymbolAddress((void**)&tgt2, g_tgt2);
    cudaGetSymbolAddress((void**)&h2,   g_h2);

    const int BKQ = BATCH * KQ;     // 12800
    const int BS  = BATCH * SEQ;    // 6272

    static bool attr_set = false;
    if (!attr_set) {
        cudaFuncSetAttribute(mma_gemm<true,  false, true >, cudaFuncAttributeMaxDynamicSharedMemorySize, SMEM_GEMM);
        cudaFuncSetAttribute(mma_gemm<false, true,  false>, cudaFuncAttributeMaxDynamicSharedMemorySize, SMEM_GEMM);
        cudaFuncSetAttribute(mma_gemm<false, false, true >, cudaFuncAttributeMaxDynamicSharedMemorySize, SMEM_GEMM);
        cudaFuncSetAttribute(mma_gemm_kvq, cudaFuncAttributeMaxDynamicSharedMemorySize, SMEM_GEMM);
        cudaFuncSetAttribute(attn_mma, cudaFuncAttributeMaxDynamicSharedMemorySize, SMEM_ATTN);
        attr_set = true;
    }

    // 0) conversions (3 launches)
    xT_cvt<<<dim3(FDIM / 32, 2, BATCH), dim3(32, 8)>>>(x, xT);
    cvt_f16_multi<<<dim3(384, 5), 256>>>(
        W_embed, We,  FDIM * D / 4,
        wo,      woc, D * D / 4,
        w1,      w1c, D * FF / 4,
        w2,      w2c, FF * D / 4,
        wq,      wqc, D * D / 4);
    cvt_wkv<<<(D * DKV / 4 + 255) / 256, 256>>>(wk, wv, bk, bv, wkvc, bkv);

    // 1) embed: mem = relu(xT @ W_embed + b_embed) -> fp16   (6272 x 768 x 2048)
    mma_gemm<true, false, true><<<dim3(D / TBN, BS / TBM), 256, SMEM_GEMM>>>(
        xT, We, b_embed, nullptr, memh, BS, D, FDIM);

    // 2) tgt_ln = LN(2 * query_embed) -> fp32 + fp16 (padded to 128 rows)
    ln_query<<<128, 256>>>(query_embed, g1, be1, tln, tlnh);

    // 3+4) fused K|V projection (6272x1536x768) + q projection (128x768x768)
    mma_gemm_kvq<<<dim3(DKV / TBN, BS / TBM + 1), 256, SMEM_GEMM>>>(
        memh, wkvc, bkv, kvh, tlnh, wqc, bq, qh);

    // 5) attention (tensor-core, 8 warps) -> ctx fp16
    attn_mma<<<dim3(NHEAD, BATCH), 256, SMEM_ATTN>>>(qh, kvh, ctxh);

    // 6) attn_out = ctx @ wo + bo -> fp32
    mma_gemm<false, true, false><<<dim3(D / TBN, BKQ / TBM), 256, SMEM_GEMM>>>(
        ctxh, woc, bo, tmp, nullptr, BKQ, D, D);

    // 7) tgt2 = LN(tgt_ln + attn_out) -> fp32 + fp16 (warp-per-row)
    ln_residual_w<<<BKQ / 8, 256>>>(tln, tmp, g2, be2, tgt2, t2h);

    // 8) FFN
    mma_gemm<true, false, true><<<dim3(FF / TBN, BKQ / TBM), 256, SMEM_GEMM>>>(
        t2h, w1c, b1, nullptr, h1h, BKQ, FF, D);
    mma_gemm<false, true, false><<<dim3(D / TBN, BKQ / TBM), 256, SMEM_GEMM>>>(
        h1h, w2c, b2, h2, nullptr, BKQ, D, FF);

    // 9+10) fused LN + group FC -> logits
    groupfc_ln<<<dim3(KQ, 4), 256>>>(tgt2, h2, g3, be3, dup_pool, dup_bias, out);
}

// round 17
// speedup vs baseline: 1.4712x; 1.0118x over previous
#include <cuda_runtime.h>
#include <cuda_fp16.h>
#include <math.h>
#include <stdint.h>

// ---------------------------------------------------------------------------
// Problem constants
// ---------------------------------------------------------------------------
#define BATCH 128
#define SEQ   49
#define FDIM  2048
#define D     768
#define KQ    100
#define NHEAD 8
#define HD    96
#define FF    2048
#define NC    1000
#define GRP   10
#define EPS   1e-5f
#define DKV   1536      // concatenated K|V width

// ---------------------------------------------------------------------------
// Scratch (static device globals; no allocation allowed)
// ---------------------------------------------------------------------------
__device__ __half g_xT  [BATCH * SEQ * FDIM];
__device__ __half g_memh[BATCH * SEQ * D];
__device__ __half g_ctxh[BATCH * KQ * D];
__device__ __half g_t2h [BATCH * KQ * D];
__device__ __half g_h1h [BATCH * KQ * FF];
__device__ __half g_tlnh[128 * D];             // fp16 tgt_ln padded to 128 rows
__device__ __half g_qh  [128 * D];             // fp16 q projection
__device__ __half g_kvh [BATCH * SEQ * DKV];   // fp16 K|V fused projection
// fp16 weights ([K, N] row-major); wkv = concat(wk, wv) along N
__device__ __half g_We [FDIM * D];
__device__ __half g_wq [D * D];
__device__ __half g_wkv[D * DKV];
__device__ __half g_wo [D * D];
__device__ __half g_w1 [D * FF];
__device__ __half g_w2 [FF * D];
__device__ float  g_bkv[DKV];
// fp32 buffers
__device__ float g_tgtln[KQ * D];
__device__ float g_tmp  [BATCH * KQ * D];
__device__ float g_tgt2 [BATCH * KQ * D];
__device__ float g_h2   [BATCH * KQ * D];

// ---------------------------------------------------------------------------
// PTX helpers
// ---------------------------------------------------------------------------
__device__ __forceinline__ uint32_t smem_u32(const void* p) {
    return (uint32_t)__cvta_generic_to_shared(p);
}
__device__ __forceinline__ void ldsm_x4(uint32_t* d, uint32_t addr) {
    asm volatile("ldmatrix.sync.aligned.m8n8.x4.shared.b16 {%0,%1,%2,%3}, [%4];"
        : "=r"(d[0]), "=r"(d[1]), "=r"(d[2]), "=r"(d[3]) : "r"(addr));
}
__device__ __forceinline__ void ldsm_x4t(uint32_t* d, uint32_t addr) {
    asm volatile("ldmatrix.sync.aligned.m8n8.x4.trans.shared.b16 {%0,%1,%2,%3}, [%4];"
        : "=r"(d[0]), "=r"(d[1]), "=r"(d[2]), "=r"(d[3]) : "r"(addr));
}
__device__ __forceinline__ void mma16816h(float* c, const uint32_t* a, const uint32_t* b) {
    asm volatile("mma.sync.aligned.m16n8k16.row.col.f32.f16.f16.f32 "
        "{%0,%1,%2,%3}, {%4,%5,%6,%7}, {%8,%9}, {%0,%1,%2,%3};"
        : "+f"(c[0]), "+f"(c[1]), "+f"(c[2]), "+f"(c[3])
        : "r"(a[0]), "r"(a[1]), "r"(a[2]), "r"(a[3]), "r"(b[0]), "r"(b[1]));
}
__device__ __forceinline__ void mma16816h2(float* c, const uint32_t* a,
                                           uint32_t b0, uint32_t b1) {
    asm volatile("mma.sync.aligned.m16n8k16.row.col.f32.f16.f16.f32 "
        "{%0,%1,%2,%3}, {%4,%5,%6,%7}, {%8,%9}, {%0,%1,%2,%3};"
        : "+f"(c[0]), "+f"(c[1]), "+f"(c[2]), "+f"(c[3])
        : "r"(a[0]), "r"(a[1]), "r"(a[2]), "r"(a[3]), "r"(b0), "r"(b1));
}
__device__ __forceinline__ void cp_async16(uint32_t dst, const void* src) {
    asm volatile("cp.async.cg.shared.global [%0], [%1], 16;"
        :: "r"(dst), "l"(src) : "memory");
}
__device__ __forceinline__ void cp_commit() {
    asm volatile("cp.async.commit_group;" ::: "memory");
}
template<int N_>
__device__ __forceinline__ void cp_wait() {
    asm volatile("cp.async.wait_group %0;" :: "n"(N_) : "memory");
}

// ---------------------------------------------------------------------------
// Tensor-core GEMM tile (R7/R10-proven config, as device function):
// C = A_fp16 @ B_fp16 + bias. CTA tile 128x128, BK=32, 256 threads
// (2Mx4N warps, warp tile 64x32), 4-stage cp.async pipeline, one
// __syncthreads per k-iter, load issued between the two k16 halves.
// 2 CTAs/SM. N%128==0, K%32==0.
// ---------------------------------------------------------------------------
#define TBM 128
#define TBN 128
#define TBK 32
#define NSTG 4
#define A_STRIDE (TBK + 8)      // 40 halfs
#define B_STRIDE (TBN + 8)      // 136 halfs
#define A_BUF (TBM * A_STRIDE)  // 5120 halfs
#define B_BUF (TBK * B_STRIDE)  // 4352 halfs
#define STAGE_HALFS (A_BUF + B_BUF)              // 9472
#define SMEM_GEMM (NSTG * STAGE_HALFS * 2)       // 75776 B

template<bool RELU, bool WF32, bool WHALF>
__device__ __forceinline__
void gemm_tile(const __half* __restrict__ A, const __half* __restrict__ B,
               const float* __restrict__ bias,
               float* __restrict__ Cf, __half* __restrict__ Ch,
               int N, int K, int m0, int n0, unsigned char* smem_raw)
{
    __half* sA = (__half*)smem_raw;               // [NSTG][A_BUF]
    __half* sB = sA + NSTG * A_BUF;               // [NSTG][B_BUF]

    const int tid  = threadIdx.x;
    const int lane = tid & 31;
    const int warp = tid >> 5;
    const int m_base = (warp & 1) * 64;
    const int n_base = (warp >> 1) * 32;

    const int ar = tid >> 2,  ac = (tid & 3) * 8;    // A: rows ar, ar+64
    const int br = tid >> 4,  bc = (tid & 15) * 8;   // B: rows br, br+16

    const uint32_t uA = smem_u32(sA);
    const uint32_t uB = smem_u32(sB);

    float acc[4][4][4];
    #pragma unroll
    for (int i = 0; i < 4; i++)
        #pragma unroll
        for (int j = 0; j < 4; j++)
            #pragma unroll
            for (int k = 0; k < 4; k++) acc[i][j][k] = 0.0f;

    auto load_async = [&](int it, int buf) {
        const int k0 = it * TBK;
        uint32_t dA = uA + (uint32_t)((buf * A_BUF + ar * A_STRIDE + ac) * 2);
        const __half* gA = A + (size_t)(m0 + ar) * K + k0 + ac;
        cp_async16(dA, gA);
        cp_async16(dA + (uint32_t)(64 * A_STRIDE * 2), gA + (size_t)64 * K);
        uint32_t dB = uB + (uint32_t)((buf * B_BUF + br * B_STRIDE + bc) * 2);
        const __half* gB = B + (size_t)(k0 + br) * N + n0 + bc;
        cp_async16(dB, gB);
        cp_async16(dB + (uint32_t)(16 * B_STRIDE * 2), gB + (size_t)16 * N);
    };

    const int lr = lane & 15;
    const int lc = lane >> 4;

    auto compute_k = [&](int buf, int kk) {
        uint32_t a[4][4], b[2][4];
        #pragma unroll
        for (int mt = 0; mt < 4; mt++) {
            uint32_t off = (uint32_t)((buf * A_BUF +
                (m_base + mt * 16 + lr) * A_STRIDE + kk + lc * 8) * 2);
            ldsm_x4(a[mt], uA + off);
        }
        #pragma unroll
        for (int ng = 0; ng < 2; ng++) {
            uint32_t off = (uint32_t)((buf * B_BUF +
                (kk + lr) * B_STRIDE + n_base + ng * 16 + lc * 8) * 2);
            ldsm_x4t(b[ng], uB + off);
        }
        #pragma unroll
        for (int mt = 0; mt < 4; mt++)
            #pragma unroll
            for (int ng = 0; ng < 2; ng++)
                #pragma unroll
                for (int h = 0; h < 2; h++)
                    mma16816h(acc[mt][ng * 2 + h], a[mt], &b[ng][2 * h]);
    };

    const int niter = K / TBK;
    #pragma unroll
    for (int s = 0; s < NSTG - 1; s++) {
        if (s < niter) load_async(s, s);
        cp_commit();
    }
    int buf = 0;
    for (int it = 0; it < niter; it++) {
        cp_wait<NSTG - 2>();
        __syncthreads();
        compute_k(buf, 0);
        const int nx = it + NSTG - 1;
        if (nx < niter) {
            int nbuf = buf - 1; if (nbuf < 0) nbuf += NSTG;
            load_async(nx, nbuf);
        }
        cp_commit();
        compute_k(buf, 16);
        if (++buf == NSTG) buf = 0;
    }

    // epilogue
    #pragma unroll
    for (int mt = 0; mt < 4; mt++) {
        int r0 = m0 + m_base + mt * 16 + (lane >> 2);
        #pragma unroll
        for (int j = 0; j < 4; j++) {
            int col = n0 + n_base + j * 8 + (lane & 3) * 2;
            float bx = bias[col], by = bias[col + 1];
            float* c = acc[mt][j];
            float v00 = c[0] + bx, v01 = c[1] + by;
            float v10 = c[2] + bx, v11 = c[3] + by;
            if (RELU) {
                v00 = fmaxf(v00, 0.f); v01 = fmaxf(v01, 0.f);
                v10 = fmaxf(v10, 0.f); v11 = fmaxf(v11, 0.f);
            }
            if (WF32) {
                *(float2*)(Cf + (size_t)r0 * N + col)       = make_float2(v00, v01);
                *(float2*)(Cf + (size_t)(r0 + 8) * N + col) = make_float2(v10, v11);
            }
            if (WHALF) {
                __half2 p0; p0.x = __float2half_rn(v00); p0.y = __float2half_rn(v01);
                __half2 p1; p1.x = __float2half_rn(v10); p1.y = __float2half_rn(v11);
                *(__half2*)(Ch + (size_t)r0 * N + col)       = p0;
                *(__half2*)(Ch + (size_t)(r0 + 8) * N + col) = p1;
            }
        }
    }
}

template<bool RELU, bool WF32, bool WHALF>
__global__ __launch_bounds__(256, 2)
void mma_gemm(const __half* __restrict__ A, const __half* __restrict__ B,
              const float* __restrict__ bias,
              float* __restrict__ Cf, __half* __restrict__ Ch,
              int M, int N, int K)
{
    extern __shared__ __align__(16) unsigned char smem_raw[];
    (void)M;
    gemm_tile<RELU, WF32, WHALF>(A, B, bias, Cf, Ch, N, K,
                                 blockIdx.y * TBM, blockIdx.x * TBN, smem_raw);
}

// Fused KV-projection + q-projection GEMM.
// grid = (12, 50): rows 0..48 = KV tiles (N=DKV), row 49 = q tiles (N=D, 6 used)
__global__ __launch_bounds__(256, 2)
void mma_gemm_kvq(const __half* __restrict__ Akv, const __half* __restrict__ Bkv,
                  const float* __restrict__ bkv, __half* __restrict__ Ckv,
                  const __half* __restrict__ Aq, const __half* __restrict__ Bq,
                  const float* __restrict__ bq, __half* __restrict__ Cq)
{
    extern __shared__ __align__(16) unsigned char smem_raw[];
    if (blockIdx.y < 49) {
        gemm_tile<false, false, true>(Akv, Bkv, bkv, nullptr, Ckv, DKV, D,
                                      blockIdx.y * TBM, blockIdx.x * TBN, smem_raw);
    } else {
        if (blockIdx.x >= D / TBN) return;
        gemm_tile<false, false, true>(Aq, Bq, bq, nullptr, Cq, D, D,
                                      0, blockIdx.x * TBN, smem_raw);
    }
}

// ---------------------------------------------------------------------------
// Transpose + fp16 convert: x (B, FDIM, SEQ) -> A (B*SEQ, FDIM)
// ---------------------------------------------------------------------------
__global__ __launch_bounds__(256)
void xT_cvt(const float* __restrict__ x, __half* __restrict__ o)
{
    __shared__ float t[32][33];
    int b = blockIdx.z;
    int f0 = blockIdx.x * 32, s0 = blockIdx.y * 32;
    const float* xb = x + (size_t)b * FDIM * SEQ;
    int tx = threadIdx.x, ty = threadIdx.y;
    #pragma unroll
    for (int i = ty; i < 32; i += 8) {
        int s = s0 + tx;
        t[i][tx] = (s < SEQ) ? xb[(size_t)(f0 + i) * SEQ + s] : 0.f;
    }
    __syncthreads();
    #pragma unroll
    for (int i = ty; i < 32; i += 8) {
        int s = s0 + i, f = f0 + tx;
        if (s < SEQ)
            o[((size_t)b * SEQ + s) * FDIM + f] = __float2half_rn(t[tx][i]);
    }
}

// ---------------------------------------------------------------------------
// Merged fp32 -> fp16 weight conversion: 5 jobs in one launch (blockIdx.y)
// ---------------------------------------------------------------------------
__global__ __launch_bounds__(256)
void cvt_f16_multi(const float* __restrict__ s0, __half* __restrict__ d0, int n0,
                   const float* __restrict__ s1, __half* __restrict__ d1, int n1,
                   const float* __restrict__ s2, __half* __restrict__ d2, int n2,
                   const float* __restrict__ s3, __half* __restrict__ d3, int n3,
                   const float* __restrict__ s4, __half* __restrict__ d4, int n4)
{
    const float* s; __half* d; int n;
    switch (blockIdx.y) {
        case 0: s = s0; d = d0; n = n0; break;
        case 1: s = s1; d = d1; n = n1; break;
        case 2: s = s2; d = d2; n = n2; break;
        case 3: s = s3; d = d3; n = n3; break;
        default: s = s4; d = d4; n = n4; break;
    }
    for (int i = blockIdx.x * 256 + threadIdx.x; i < n; i += gridDim.x * 256) {
        float4 v = ((const float4*)s)[i];
        __half2 h0, h1;
        h0.x = __float2half_rn(v.x); h0.y = __float2half_rn(v.y);
        h1.x = __float2half_rn(v.z); h1.y = __float2half_rn(v.w);
        ((__half2*)d)[i * 2]     = h0;
        ((__half2*)d)[i * 2 + 1] = h1;
    }
}

// ---------------------------------------------------------------------------
// wk|wv -> concatenated fp16 wkv [D, 1536] + bkv = concat(bk, bv)
// ---------------------------------------------------------------------------
__global__ __launch_bounds__(256)
void cvt_wkv(const float* __restrict__ wk, const float* __restrict__ wv,
             const float* __restrict__ bk, const float* __restrict__ bv,
             __half* __restrict__ o, float* __restrict__ ob)
{
    int gt = blockIdx.x * 256 + threadIdx.x;
    if (gt < DKV) ob[gt] = (gt < D) ? bk[gt] : bv[gt - D];
    if (gt < D * DKV / 4) {
        int k = gt / (DKV / 4);
        int c4 = gt - k * (DKV / 4);
        int n = c4 * 4;
        const float* src = (n < D) ? (wk + (size_t)k * D + n)
                                   : (wv + (size_t)k * D + n - D);
        float4 v = *(const float4*)src;
        __half2 h0, h1;
        h0.x = __float2half_rn(v.x); h0.y = __float2half_rn(v.y);
        h1.x = __float2half_rn(v.z); h1.y = __float2half_rn(v.w);
        ((__half2*)o)[gt * 2]     = h0;
        ((__half2*)o)[gt * 2 + 1] = h1;
    }
}

// ---------------------------------------------------------------------------
// Block reduction helper
// ---------------------------------------------------------------------------
__device__ __forceinline__ float block_sum(float v, float* sred) {
    int lane = threadIdx.x & 31, w = threadIdx.x >> 5;
    #pragma unroll
    for (int o = 16; o > 0; o >>= 1) v += __shfl_down_sync(0xffffffffu, v, o);
    if (lane == 0) sred[w] = v;
    __syncthreads();
    float s = (threadIdx.x < 8) ? sred[threadIdx.x] : 0.0f;
    if (w == 0) {
        #pragma unroll
        for (int o = 4; o > 0; o >>= 1) s += __shfl_down_sync(0xffffffffu, s, o);
        if (lane == 0) sred[0] = s;
    }
    __syncthreads();
    float r = sred[0];
    __syncthreads();
    return r;
}

// ---------------------------------------------------------------------------
// tgt_ln = layernorm(2 * query_embed) * g1 + be1
// grid = 128 rows: rows >= 100 write fp16 zeros (padding for the q GEMM).
// ---------------------------------------------------------------------------
__global__ __launch_bounds__(256)
void ln_query(const float* __restrict__ qe, const float* __restrict__ g,
              const float* __restrict__ be, float* __restrict__ out,
              __half* __restrict__ oh)
{
    __shared__ float sred[8];
    int r = blockIdx.x, t = threadIdx.x;
    if (r >= KQ) {
        #pragma unroll
        for (int i = 0; i < 3; i++)
            oh[(size_t)r * D + t + i * 256] = __float2half_rn(0.0f);
        return;
    }
    float v[3];
    float s = 0.0f;
    #pragma unroll
    for (int i = 0; i < 3; i++) { v[i] = 2.0f * qe[(size_t)r * D + t + i * 256]; s += v[i]; }
    float mean = block_sum(s, sred) * (1.0f / D);
    float vs = 0.0f;
    #pragma unroll
    for (int i = 0; i < 3; i++) { float d = v[i] - mean; vs += d * d; }
    float var = block_sum(vs, sred) * (1.0f / D);
    float inv = rsqrtf(var + EPS);
    #pragma unroll
    for (int i = 0; i < 3; i++) {
        int c = t + i * 256;
        float o = (v[i] - mean) * inv * g[c] + be[c];
        out[(size_t)r * D + c] = o;
        oh[(size_t)r * D + c] = __float2half_rn(o);
    }
}

// ---------------------------------------------------------------------------
// out = LN(res[r % KQ] + inp[r]) ; warp-per-row, 8 rows/block. grid = rows/8.
// ---------------------------------------------------------------------------
__global__ __launch_bounds__(256)
void ln_residual_w(const float* __restrict__ res, const float* __restrict__ inp,
                   const float* __restrict__ g, const float* __restrict__ be,
                   float* __restrict__ out, __half* __restrict__ oh)
{
    const int warp = threadIdx.x >> 5, lane = threadIdx.x & 31;
    long r = (long)blockIdx.x * 8 + warp;
    long rr = r % KQ;
    const float* rp = res + rr * D;
    const float* ip = inp + r * D;

    float v[24];
    float s = 0.0f;
    #pragma unroll
    for (int i = 0; i < 24; i++) {
        int c = lane + i * 32;
        v[i] = rp[c] + ip[c];
        s += v[i];
    }
    #pragma unroll
    for (int o = 16; o > 0; o >>= 1) s += __shfl_xor_sync(0xffffffffu, s, o);
    float mean = s * (1.0f / D);
    float vs = 0.0f;
    #pragma unroll
    for (int i = 0; i < 24; i++) { float d = v[i] - mean; vs += d * d; }
    #pragma unroll
    for (int o = 16; o > 0; o >>= 1) vs += __shfl_xor_sync(0xffffffffu, vs, o);
    float inv = rsqrtf(vs * (1.0f / D) + EPS);
    #pragma unroll
    for (int i = 0; i < 24; i++) {
        int c = lane + i * 32;
        float o = (v[i] - mean) * inv * g[c] + be[c];
        out[r * D + c] = o;
        oh[r * D + c] = __float2half_rn(o);
    }
}

// ---------------------------------------------------------------------------
// Tensor-core cross attention, 8 warps, 4 BATCHES PER BLOCK (Q staged once).
// grid=(NHEAD, BATCH/4), 256 threads. Per-row math identical to R15.
// Dynamic smem: Q[128x104] + K[64x104] + V[64x104] fp16 = 53248 B.
// ---------------------------------------------------------------------------
#define AST 104                                // smem row stride (halfs)
#define SMEM_ATTN ((128 + 64 + 64) * AST * 2)  // 53248 B
#define ATT_BPB 4                              // batches per block

__global__ __launch_bounds__(256)
void attn_mma(const __half* __restrict__ Q, const __half* __restrict__ KV,
              __half* __restrict__ ch)
{
    extern __shared__ __align__(16) __half smA[];
    __half* Qs = smA;                 // [128][AST]
    __half* Ks = Qs + 128 * AST;      // [64][AST] (rows >= SEQ zero)
    __half* Vs = Ks + 64 * AST;       // [64][AST] (rows >= SEQ zero)
    const int hh = blockIdx.x;
    const int b0 = blockIdx.y * ATT_BPB;
    const int t = threadIdx.x;
    const int lane = t & 31, warp = t >> 5;

    // stage Q once (reused across all batches of this block)
    for (int idx = t; idx < 128 * 48; idx += 256) {
        int r = idx / 48, d2 = idx - r * 48;
        ((__half2*)(Qs + r * AST))[d2] =
            *(const __half2*)(Q + (size_t)r * D + hh * HD + 2 * d2);
    }

    const int lr = lane & 15, lc = lane >> 4;
    const int m_base = warp * 16;
    const uint32_t uQ = smem_u32(Qs), uK = smem_u32(Ks), uV = smem_u32(Vs);
    const float scale = 0.102062072615966f;   // 1/sqrt(96)
    const int c0 = (lane & 3) * 2;

    for (int bi = 0; bi < ATT_BPB; bi++) {
        const int b = b0 + bi;
        // stage K, V for this batch
        for (int idx = t; idx < 64 * 48; idx += 256) {
            int s = idx / 48, d2 = idx - s * 48;
            __half2 kk2, vv2;
            if (s < SEQ) {
                size_t off = ((size_t)b * SEQ + s) * DKV + hh * HD + 2 * d2;
                kk2 = *(const __half2*)(KV + off);
                vv2 = *(const __half2*)(KV + off + D);
            } else {
                kk2.x = __float2half_rn(0.f); kk2.y = kk2.x;
                vv2 = kk2;
            }
            ((__half2*)(Ks + s * AST))[d2] = kk2;
            ((__half2*)(Vs + s * AST))[d2] = vv2;
        }
        __syncthreads();

        // ---- S = Q K^T : sacc[j][*], j = n8 tile 0..7 (cols 0..63) ----
        float sacc[8][4];
        #pragma unroll
        for (int j = 0; j < 8; j++)
            #pragma unroll
            for (int k = 0; k < 4; k++) sacc[j][k] = 0.0f;

        #pragma unroll
        for (int kk = 0; kk < HD; kk += 16) {
            uint32_t a[4];
            ldsm_x4(a, uQ + (uint32_t)(((m_base + lr) * AST + kk + lc * 8) * 2));
            uint32_t kb[4][4];
            #pragma unroll
            for (int ng = 0; ng < 4; ng++)
                ldsm_x4(kb[ng], uK + (uint32_t)(((ng * 16 + lr) * AST + kk + lc * 8) * 2));
            #pragma unroll
            for (int ng = 0; ng < 4; ng++) {
                // K stored [n][k]: frag pairs (r0,r2) and (r1,r3)
                mma16816h2(sacc[2 * ng],     a, kb[ng][0], kb[ng][2]);
                mma16816h2(sacc[2 * ng + 1], a, kb[ng][1], kb[ng][3]);
            }
        }

        // ---- fragment softmax (cols >= SEQ masked) ----
        float minv[2];
        {
            float m0 = -1e30f, m1 = -1e30f;
            #pragma unroll
            for (int j = 0; j < 8; j++) {
                int n = j * 8 + c0;
                float* c = sacc[j];
                c[0] = (n     < SEQ) ? c[0] * scale : -1e30f;
                c[1] = (n + 1 < SEQ) ? c[1] * scale : -1e30f;
                c[2] = (n     < SEQ) ? c[2] * scale : -1e30f;
                c[3] = (n + 1 < SEQ) ? c[3] * scale : -1e30f;
                m0 = fmaxf(m0, fmaxf(c[0], c[1]));
                m1 = fmaxf(m1, fmaxf(c[2], c[3]));
            }
            m0 = fmaxf(m0, __shfl_xor_sync(0xffffffffu, m0, 1));
            m0 = fmaxf(m0, __shfl_xor_sync(0xffffffffu, m0, 2));
            m1 = fmaxf(m1, __shfl_xor_sync(0xffffffffu, m1, 1));
            m1 = fmaxf(m1, __shfl_xor_sync(0xffffffffu, m1, 2));
            float l0 = 0.f, l1 = 0.f;
            #pragma unroll
            for (int j = 0; j < 8; j++) {
                float* c = sacc[j];
                c[0] = __expf(c[0] - m0); c[1] = __expf(c[1] - m0);
                c[2] = __expf(c[2] - m1); c[3] = __expf(c[3] - m1);
                l0 += c[0] + c[1];
                l1 += c[2] + c[3];
            }
            l0 += __shfl_xor_sync(0xffffffffu, l0, 1);
            l0 += __shfl_xor_sync(0xffffffffu, l0, 2);
            l1 += __shfl_xor_sync(0xffffffffu, l1, 1);
            l1 += __shfl_xor_sync(0xffffffffu, l1, 2);
            minv[0] = 1.0f / l0;
            minv[1] = 1.0f / l1;
        }

        // ---- ctx = P V : cacc[j2][*], j2 = n8 tile 0..11 (d = 0..95) ----
        float cacc[12][4];
        #pragma unroll
        for (int j = 0; j < 12; j++)
            #pragma unroll
            for (int k = 0; k < 4; k++) cacc[j][k] = 0.0f;

        #pragma unroll
        for (int kt = 0; kt < 4; kt++) {          // s dim 64 = 4 x k16
            uint32_t pa[4];
            {
                __half2 h;
                h = __floats2half2_rn(sacc[2 * kt][0],     sacc[2 * kt][1]);
                pa[0] = *(uint32_t*)&h;
                h = __floats2half2_rn(sacc[2 * kt][2],     sacc[2 * kt][3]);
                pa[1] = *(uint32_t*)&h;
                h = __floats2half2_rn(sacc[2 * kt + 1][0], sacc[2 * kt + 1][1]);
                pa[2] = *(uint32_t*)&h;
                h = __floats2half2_rn(sacc[2 * kt + 1][2], sacc[2 * kt + 1][3]);
                pa[3] = *(uint32_t*)&h;
            }
            #pragma unroll
            for (int ng = 0; ng < 3; ng++) {      // d dim 96 = 3 x 32
                uint32_t vb[4];
                ldsm_x4t(vb, uV + (uint32_t)(((kt * 16 + lr) * AST + ng * 32 + lc * 8) * 2));
                mma16816h2(cacc[4 * ng],     pa, vb[0], vb[1]);
                mma16816h2(cacc[4 * ng + 1], pa, vb[2], vb[3]);
                uint32_t vb2[4];
                ldsm_x4t(vb2, uV + (uint32_t)(((kt * 16 + lr) * AST + ng * 32 + 16 + lc * 8) * 2));
                mma16816h2(cacc[4 * ng + 2], pa, vb2[0], vb2[1]);
                mma16816h2(cacc[4 * ng + 3], pa, vb2[2], vb2[3]);
            }
        }

        // ---- store ctx rows < KQ, scaled by 1/l ----
        {
            int q0 = m_base + (lane >> 2);
            #pragma unroll
            for (int rr = 0; rr < 2; rr++) {
                int q = q0 + rr * 8;
                if (q < KQ) {
                    float iv = minv[rr];
                    size_t ob = ((size_t)b * KQ + q) * D + hh * HD;
                    #pragma unroll
                    for (int j2 = 0; j2 < 12; j2++) {
                        int d = j2 * 8 + c0;
                        float* c = cacc[j2];
                        __half2 p;
                        p.x = __float2half_rn(c[2 * rr]     * iv);
                        p.y = __float2half_rn(c[2 * rr + 1] * iv);
                        *(__half2*)(ch + ob + d) = p;
                    }
                }
            }
        }
        // guard K/V smem reuse for next batch
        __syncthreads();
    }
}

// ---------------------------------------------------------------------------
// GroupFC with fused final LayerNorm.
// grid = (KQ, 4), 256 threads, 32 batches/block, warp-per-row LN + dot.
// ---------------------------------------------------------------------------
#define GFC_BPB 32
__global__ __launch_bounds__(256)
void groupfc_ln(const float* __restrict__ R, const float* __restrict__ I,
                const float* __restrict__ g3, const float* __restrict__ be3,
                const float* __restrict__ P, const float* __restrict__ db,
                float* __restrict__ out)
{
    __shared__ float sP[D * GRP];   // 30720 B
    const int k  = blockIdx.x;
    const int b0 = blockIdx.y * GFC_BPB;
    const float* pp = P + (size_t)k * D * GRP;
    for (int i = threadIdx.x; i < D * GRP; i += 256) sP[i] = pp[i];
    __syncthreads();

    const int warp = threadIdx.x >> 5, lane = threadIdx.x & 31;
    #pragma unroll
    for (int bi = 0; bi < GFC_BPB / 8; bi++) {
        int b = b0 + warp + bi * 8;
        size_t row = (size_t)b * KQ + k;
        const float* rp = R + row * D;
        const float* ip = I + row * D;

        float v[24];
        float s = 0.0f;
        #pragma unroll
        for (int i = 0; i < 24; i++) {
            int c = lane + i * 32;
            v[i] = rp[c] + ip[c];
            s += v[i];
        }
        #pragma unroll
        for (int o = 16; o > 0; o >>= 1) s += __shfl_xor_sync(0xffffffffu, s, o);
        float mean = s * (1.0f / D);
        float vs = 0.0f;
        #pragma unroll
        for (int i = 0; i < 24; i++) { float d = v[i] - mean; vs += d * d; }
        #pragma unroll
        for (int o = 16; o > 0; o >>= 1) vs += __shfl_xor_sync(0xffffffffu, vs, o);
        float inv = rsqrtf(vs * (1.0f / D) + EPS);

        float acc[GRP] = {};
        #pragma unroll
        for (int i = 0; i < 24; i++) {
            int c = lane + i * 32;
            float h = (v[i] - mean) * inv * g3[c] + be3[c];
            const float* q = sP + c * GRP;
            #pragma unroll
            for (int g = 0; g < GRP; g++) acc[g] += h * q[g];
        }
        #pragma unroll
        for (int g = 0; g < GRP; g++)
            #pragma unroll
            for (int o = 16; o > 0; o >>= 1)
                acc[g] += __shfl_xor_sync(0xffffffffu, acc[g], o);
        if (lane < GRP) {
            float val = 0.0f;
            #pragma unroll
            for (int g = 0; g < GRP; g++) if (lane == g) val = acc[g];
            out[(size_t)b * NC + k * GRP + lane] = val + db[k * GRP + lane];
        }
    }
}

// ---------------------------------------------------------------------------
// Host launcher
// ---------------------------------------------------------------------------
extern "C" void kernel_launch(void* const* d_in, const int* in_sizes, int n_in,
                              void* d_out, int out_size)
{
    (void)in_sizes; (void)n_in; (void)out_size;
    const float* x        = (const float*)d_in[0];
    const float* W_embed  = (const float*)d_in[1];
    const float* b_embed  = (const float*)d_in[2];
    const float* query_embed = (const float*)d_in[3];
    const float* wq = (const float*)d_in[4];
    const float* wk = (const float*)d_in[5];
    const float* wv = (const float*)d_in[6];
    const float* bq = (const float*)d_in[7];
    const float* bk = (const float*)d_in[8];
    const float* bv = (const float*)d_in[9];
    const float* wo = (const float*)d_in[10];
    const float* bo = (const float*)d_in[11];
    const float* w1 = (const float*)d_in[12];
    const float* b1 = (const float*)d_in[13];
    const float* w2 = (const float*)d_in[14];
    const float* b2 = (const float*)d_in[15];
    const float* g1 = (const float*)d_in[16];
    const float* be1= (const float*)d_in[17];
    const float* g2 = (const float*)d_in[18];
    const float* be2= (const float*)d_in[19];
    const float* g3 = (const float*)d_in[20];
    const float* be3= (const float*)d_in[21];
    const float* dup_pool = (const float*)d_in[22];
    const float* dup_bias = (const float*)d_in[23];
    float* out = (float*)d_out;

    __half *xT, *memh, *ctxh, *t2h, *h1h, *tlnh, *qh, *kvh;
    __half *We, *wqc, *wkvc, *woc, *w1c, *w2c;
    float *bkv, *tln, *tmp, *tgt2, *h2;
    cudaGetSymbolAddress((void**)&xT,   g_xT);
    cudaGetSymbolAddress((void**)&memh, g_memh);
    cudaGetSymbolAddress((void**)&ctxh, g_ctxh);
    cudaGetSymbolAddress((void**)&t2h,  g_t2h);
    cudaGetSymbolAddress((void**)&h1h,  g_h1h);
    cudaGetSymbolAddress((void**)&tlnh, g_tlnh);
    cudaGetSymbolAddress((void**)&qh,   g_qh);
    cudaGetSymbolAddress((void**)&kvh,  g_kvh);
    cudaGetSymbolAddress((void**)&We,   g_We);
    cudaGetSymbolAddress((void**)&wqc,  g_wq);
    cudaGetSymbolAddress((void**)&wkvc, g_wkv);
    cudaGetSymbolAddress((void**)&woc,  g_wo);
    cudaGetSymbolAddress((void**)&w1c,  g_w1);
    cudaGetSymbolAddress((void**)&w2c,  g_w2);
    cudaGetSymbolAddress((void**)&bkv,  g_bkv);
    cudaGetSymbolAddress((void**)&tln,  g_tgtln);
    cudaGetSymbolAddress((void**)&tmp,  g_tmp);
    cudaGetSymbolAddress((void**)&tgt2, g_tgt2);
    cudaGetSymbolAddress((void**)&h2,   g_h2);

    const int BKQ = BATCH * KQ;     // 12800
    const int BS  = BATCH * SEQ;    // 6272

    static bool attr_set = false;
    if (!attr_set) {
        cudaFuncSetAttribute(mma_gemm<true,  false, true >, cudaFuncAttributeMaxDynamicSharedMemorySize, SMEM_GEMM);
        cudaFuncSetAttribute(mma_gemm<false, true,  false>, cudaFuncAttributeMaxDynamicSharedMemorySize, SMEM_GEMM);
        cudaFuncSetAttribute(mma_gemm<false, false, true >, cudaFuncAttributeMaxDynamicSharedMemorySize, SMEM_GEMM);
        cudaFuncSetAttribute(mma_gemm_kvq, cudaFuncAttributeMaxDynamicSharedMemorySize, SMEM_GEMM);
        cudaFuncSetAttribute(attn_mma, cudaFuncAttributeMaxDynamicSharedMemorySize, SMEM_ATTN);
        attr_set = true;
    }

    // 0) conversions (3 launches)
    xT_cvt<<<dim3(FDIM / 32, 2, BATCH), dim3(32, 8)>>>(x, xT);
    cvt_f16_multi<<<dim3(384, 5), 256>>>(
        W_embed, We,  FDIM * D / 4,
        wo,      woc, D * D / 4,
        w1,      w1c, D * FF / 4,
        w2,      w2c, FF * D / 4,
        wq,      wqc, D * D / 4);
    cvt_wkv<<<(D * DKV / 4 + 255) / 256, 256>>>(wk, wv, bk, bv, wkvc, bkv);

    // 1) embed: mem = relu(xT @ W_embed + b_embed) -> fp16   (6272 x 768 x 2048)
    mma_gemm<true, false, true><<<dim3(D / TBN, BS / TBM), 256, SMEM_GEMM>>>(
        xT, We, b_embed, nullptr, memh, BS, D, FDIM);

    // 2) tgt_ln = LN(2 * query_embed) -> fp32 + fp16 (padded to 128 rows)
    ln_query<<<128, 256>>>(query_embed, g1, be1, tln, tlnh);

    // 3+4) fused K|V projection (6272x1536x768) + q projection (128x768x768)
    mma_gemm_kvq<<<dim3(DKV / TBN, BS / TBM + 1), 256, SMEM_GEMM>>>(
        memh, wkvc, bkv, kvh, tlnh, wqc, bq, qh);

    // 5) attention (tensor-core, 8 warps, 4 batches/block) -> ctx fp16
    attn_mma<<<dim3(NHEAD, BATCH / ATT_BPB), 256, SMEM_ATTN>>>(qh, kvh, ctxh);

    // 6) attn_out = ctx @ wo + bo -> fp32
    mma_gemm<false, true, false><<<dim3(D / TBN, BKQ / TBM), 256, SMEM_GEMM>>>(
        ctxh, woc, bo, tmp, nullptr, BKQ, D, D);

    // 7) tgt2 = LN(tgt_ln + attn_out) -> fp32 + fp16 (warp-per-row)
    ln_residual_w<<<BKQ / 8, 256>>>(tln, tmp, g2, be2, tgt2, t2h);

    // 8) FFN
    mma_gemm<true, false, true><<<dim3(FF / TBN, BKQ / TBM), 256, SMEM_GEMM>>>(
        t2h, w1c, b1, nullptr, h1h, BKQ, FF, D);
    mma_gemm<false, true, false><<<dim3(D / TBN, BKQ / TBM), 256, SMEM_GEMM>>>(
        h1h, w2c, b2, h2, nullptr, BKQ, D, FF);

    // 9+10) fused LN + group FC -> logits
    groupfc_ln<<<dim3(KQ, 4), 256>>>(tgt2, h2, g3, be3, dup_pool, dup_bias, out);
}